// round 1
// baseline (speedup 1.0000x reference)
#include <cuda_runtime.h>
#include <math.h>

// Problem constants
#define Bsz 2
#define Sq  2048
#define Dm  512
#define Vv  32000
#define Ll  3
#define ROWS (Bsz*Sq)      // 4096
#define BD   (ROWS*Dm)     // 2097152 floats per activation buffer
#define SSZ  (Bsz*Sq*Sq)   // 8388608 floats for attention scores
#define INV_SCALE 0.125f   // 1/sqrt(512/8)

// ---------------- scratch (static device globals: allocation-free) ----------
__device__ float g_x[BD];
__device__ float g_out[BD];
__device__ float g_h[BD];
__device__ float g_h2[BD];
__device__ float g_q[BD];
__device__ float g_k[BD];
__device__ float g_v[BD];
__device__ float g_t[BD];
__device__ float g_a[BD];
__device__ float g_s[SSZ];

// ---------------- SGEMM: C = alpha * A @ B (+bias), optional B transpose ----
// A: [M,K] row-major. B: NN -> [K,N] row-major, NT -> [N,K] row-major.
// BM=BN=128, BK=8, 256 threads, 8x8 per-thread micro-tile, float4 loads.
// Requires M%128==0, N%128==0, K%8==0 (true for all shapes here).
template<bool TB, bool HAS_BIAS>
__global__ void __launch_bounds__(256) sgemm128(
    const float* __restrict__ A, const float* __restrict__ B,
    const float* __restrict__ bias, float* __restrict__ C,
    int M, int N, int K, float alpha,
    long strideA, long strideB, long strideC)
{
    const int bz = blockIdx.z;
    A += (long)bz * strideA;
    B += (long)bz * strideB;
    C += (long)bz * strideC;

    __shared__ float As[8][128];
    __shared__ float Bs[8][128];

    const int tid  = threadIdx.x;
    const int cRow = blockIdx.y;   // M tile
    const int cCol = blockIdx.x;   // N tile
    const int tRow = (tid / 16) * 8;
    const int tCol = (tid % 16) * 8;

    float acc[8][8] = {};
    float regA[8], regB[8];

    // A tile loader: 128 rows x 8 cols, one float4 per thread
    const int aRow = tid >> 1;
    const int aCol = (tid & 1) * 4;
    const float* Abase = A + (long)(cRow * 128) * K;

    for (int k0 = 0; k0 < K; k0 += 8) {
        float4 a4 = *(const float4*)(Abase + (long)aRow * K + k0 + aCol);
        As[aCol+0][aRow] = a4.x;
        As[aCol+1][aRow] = a4.y;
        As[aCol+2][aRow] = a4.z;
        As[aCol+3][aRow] = a4.w;

        if (TB) {
            // B is [N,K]: load 128 n-rows x 8 k-cols, transpose into Bs[k][n]
            const int nRow = tid >> 1;
            const int kCol = (tid & 1) * 4;
            float4 b4 = *(const float4*)(B + (long)(cCol * 128 + nRow) * K + k0 + kCol);
            Bs[kCol+0][nRow] = b4.x;
            Bs[kCol+1][nRow] = b4.y;
            Bs[kCol+2][nRow] = b4.z;
            Bs[kCol+3][nRow] = b4.w;
        } else {
            // B is [K,N]: load 8 k-rows x 128 n-cols directly
            const int kRow = tid >> 5;
            const int nCol = (tid & 31) * 4;
            float4 b4 = *(const float4*)(B + (long)(k0 + kRow) * N + cCol * 128 + nCol);
            *(float4*)&Bs[kRow][nCol] = b4;
        }
        __syncthreads();

        #pragma unroll
        for (int kk = 0; kk < 8; kk++) {
            #pragma unroll
            for (int i = 0; i < 8; i++) regA[i] = As[kk][tRow + i];
            #pragma unroll
            for (int j = 0; j < 8; j++) regB[j] = Bs[kk][tCol + j];
            #pragma unroll
            for (int i = 0; i < 8; i++)
                #pragma unroll
                for (int j = 0; j < 8; j++)
                    acc[i][j] += regA[i] * regB[j];
        }
        __syncthreads();
    }

    #pragma unroll
    for (int i = 0; i < 8; i++) {
        const long r = (long)(cRow * 128 + tRow + i);
        #pragma unroll
        for (int j = 0; j < 8; j += 4) {
            const int c = cCol * 128 + tCol + j;
            float4 o;
            o.x = alpha * acc[i][j+0];
            o.y = alpha * acc[i][j+1];
            o.z = alpha * acc[i][j+2];
            o.w = alpha * acc[i][j+3];
            if (HAS_BIAS) {
                o.x += bias[c+0]; o.y += bias[c+1];
                o.z += bias[c+2]; o.w += bias[c+3];
            }
            *(float4*)(C + r * N + c) = o;
        }
    }
}

// ---------------- block reductions ----------------
__device__ __forceinline__ float blockReduceMax(float v, float* sh) {
    const int lane = threadIdx.x & 31, w = threadIdx.x >> 5;
    #pragma unroll
    for (int o = 16; o; o >>= 1) v = fmaxf(v, __shfl_xor_sync(0xffffffffu, v, o));
    if (lane == 0) sh[w] = v;
    __syncthreads();
    const int nw = (blockDim.x + 31) >> 5;
    if (w == 0) {
        float t = (lane < nw) ? sh[lane] : -INFINITY;
        #pragma unroll
        for (int o = 16; o; o >>= 1) t = fmaxf(t, __shfl_xor_sync(0xffffffffu, t, o));
        if (lane == 0) sh[0] = t;
    }
    __syncthreads();
    float r = sh[0];
    __syncthreads();
    return r;
}

__device__ __forceinline__ float blockReduceSum(float v, float* sh) {
    const int lane = threadIdx.x & 31, w = threadIdx.x >> 5;
    #pragma unroll
    for (int o = 16; o; o >>= 1) v += __shfl_xor_sync(0xffffffffu, v, o);
    if (lane == 0) sh[w] = v;
    __syncthreads();
    const int nw = (blockDim.x + 31) >> 5;
    if (w == 0) {
        float t = (lane < nw) ? sh[lane] : 0.f;
        #pragma unroll
        for (int o = 16; o; o >>= 1) t += __shfl_xor_sync(0xffffffffu, t, o);
        if (lane == 0) sh[0] = t;
    }
    __syncthreads();
    float r = sh[0];
    __syncthreads();
    return r;
}

// ---------------- row softmax (in-place), one block per row ----------------
__global__ void softmax_kernel(float* __restrict__ data, int N) {
    __shared__ float sh[32];
    float* row = data + (size_t)blockIdx.x * N;
    float m = -INFINITY;
    for (int i = threadIdx.x; i < N; i += blockDim.x) m = fmaxf(m, row[i]);
    m = blockReduceMax(m, sh);
    float s = 0.f;
    for (int i = threadIdx.x; i < N; i += blockDim.x) s += __expf(row[i] - m);
    s = blockReduceSum(s, sh);
    const float inv = 1.f / s;
    for (int i = threadIdx.x; i < N; i += blockDim.x) row[i] = __expf(row[i] - m) * inv;
}

// ---------------- fused (silu?)+residual+LayerNorm, one block (128 thr) per row
template<bool SILU, bool AFFINE>
__global__ void __launch_bounds__(128) addln_kernel(
    const float* __restrict__ a, const float* __restrict__ res,
    const float* __restrict__ g, const float* __restrict__ bta,
    float* __restrict__ out)
{
    const int row = blockIdx.x;
    const int tid = threadIdx.x;  // 128 threads * 4 = 512 = Dm
    float4 av = ((const float4*)(a   + (size_t)row * Dm))[tid];
    float4 rv = ((const float4*)(res + (size_t)row * Dm))[tid];
    float v[4] = {av.x, av.y, av.z, av.w};
    float r[4] = {rv.x, rv.y, rv.z, rv.w};

    float s = 0.f, s2 = 0.f;
    #pragma unroll
    for (int i = 0; i < 4; i++) {
        float t = SILU ? (v[i] / (1.f + __expf(-v[i]))) : v[i];
        t += r[i];
        v[i] = t;
        s += t; s2 += t * t;
    }

    __shared__ float ss[4], ss2[4];
    #pragma unroll
    for (int o = 16; o; o >>= 1) {
        s  += __shfl_xor_sync(0xffffffffu, s,  o);
        s2 += __shfl_xor_sync(0xffffffffu, s2, o);
    }
    const int w = tid >> 5, lane = tid & 31;
    if (lane == 0) { ss[w] = s; ss2[w] = s2; }
    __syncthreads();
    s  = ss[0]  + ss[1]  + ss[2]  + ss[3];
    s2 = ss2[0] + ss2[1] + ss2[2] + ss2[3];

    const float mean = s * (1.f / Dm);
    const float var  = s2 * (1.f / Dm) - mean * mean;
    const float inv  = rsqrtf(var + 1e-5f);

    float4 o4;
    float ov[4];
    #pragma unroll
    for (int i = 0; i < 4; i++) {
        float yv = (v[i] - mean) * inv;
        if (AFFINE) {
            const int c = tid * 4 + i;
            yv = yv * g[c] + bta[c];
        }
        ov[i] = yv;
    }
    o4.x = ov[0]; o4.y = ov[1]; o4.z = ov[2]; o4.w = ov[3];
    ((float4*)(out + (size_t)row * Dm))[tid] = o4;
}

// ---------------- host-side launch helpers ----------------
static void launch_gemm(const float* A, const float* B, const float* bias, float* C,
                        int M, int N, int K, float alpha, int batch,
                        long sA, long sB, long sC, bool tb)
{
    dim3 grid(N / 128, M / 128, batch), block(256);
    if (tb) {
        if (bias) sgemm128<true , true ><<<grid, block>>>(A, B, bias, C, M, N, K, alpha, sA, sB, sC);
        else      sgemm128<true , false><<<grid, block>>>(A, B, bias, C, M, N, K, alpha, sA, sB, sC);
    } else {
        if (bias) sgemm128<false, true ><<<grid, block>>>(A, B, bias, C, M, N, K, alpha, sA, sB, sC);
        else      sgemm128<false, false><<<grid, block>>>(A, B, bias, C, M, N, K, alpha, sA, sB, sC);
    }
}

// one attention block: out = LN( softmax((qsrc@wq)(ctx@wk)^T / 8) @ (ctx@wv) + resid )
static void run_attn(const float* qsrc, const float* ctx,
                     const float* wq, const float* wk, const float* wv,
                     const float* resid, float* outp,
                     float* gq, float* gk, float* gv, float* gs, float* ga)
{
    launch_gemm(qsrc, wq, nullptr, gq, ROWS, Dm, Dm, 1.f, 1, 0, 0, 0, false);
    launch_gemm(ctx,  wk, nullptr, gk, ROWS, Dm, Dm, 1.f, 1, 0, 0, 0, false);
    launch_gemm(ctx,  wv, nullptr, gv, ROWS, Dm, Dm, 1.f, 1, 0, 0, 0, false);
    // scores[b] = q[b] @ k[b]^T / SCALE     (batched NT)
    launch_gemm(gq, gk, nullptr, gs, Sq, Sq, Dm, INV_SCALE, Bsz,
                (long)Sq * Dm, (long)Sq * Dm, (long)Sq * Sq, true);
    softmax_kernel<<<ROWS, 256>>>(gs, Sq);
    // attn[b] = p[b] @ v[b]                 (batched NN)
    launch_gemm(gs, gv, nullptr, ga, Sq, Dm, Sq, 1.f, Bsz,
                (long)Sq * Sq, (long)Sq * Dm, (long)Sq * Dm, false);
    addln_kernel<false, false><<<ROWS, 128>>>(ga, resid, nullptr, nullptr, outp);
}

extern "C" void kernel_launch(void* const* d_in, const int* in_sizes, int n_in,
                              void* d_out, int out_size)
{
    const float* x       = (const float*)d_in[0];
    const float* y       = (const float*)d_in[1];
    const float* enc_wq  = (const float*)d_in[2];
    const float* enc_wk  = (const float*)d_in[3];
    const float* enc_wv  = (const float*)d_in[4];
    const float* enc_fw  = (const float*)d_in[5];
    const float* enc_fb  = (const float*)d_in[6];
    const float* enc_g   = (const float*)d_in[7];
    const float* enc_b   = (const float*)d_in[8];
    const float* dec_swq = (const float*)d_in[9];
    const float* dec_swk = (const float*)d_in[10];
    const float* dec_swv = (const float*)d_in[11];
    const float* dec_cwq = (const float*)d_in[12];
    const float* dec_cwk = (const float*)d_in[13];
    const float* dec_cwv = (const float*)d_in[14];
    const float* dec_fw  = (const float*)d_in[15];
    const float* dec_fb  = (const float*)d_in[16];
    const float* dec_g   = (const float*)d_in[17];
    const float* dec_b   = (const float*)d_in[18];
    const float* fc_w    = (const float*)d_in[19];

    float *gx, *gout, *gh, *gh2, *gq, *gk, *gv, *gt, *ga, *gs;
    cudaGetSymbolAddress((void**)&gx,   g_x);
    cudaGetSymbolAddress((void**)&gout, g_out);
    cudaGetSymbolAddress((void**)&gh,   g_h);
    cudaGetSymbolAddress((void**)&gh2,  g_h2);
    cudaGetSymbolAddress((void**)&gq,   g_q);
    cudaGetSymbolAddress((void**)&gk,   g_k);
    cudaGetSymbolAddress((void**)&gv,   g_v);
    cudaGetSymbolAddress((void**)&gt,   g_t);
    cudaGetSymbolAddress((void**)&ga,   g_a);
    cudaGetSymbolAddress((void**)&gs,   g_s);

    cudaMemcpyAsync(gx,   x, (size_t)BD * sizeof(float), cudaMemcpyDeviceToDevice);
    cudaMemcpyAsync(gout, y, (size_t)BD * sizeof(float), cudaMemcpyDeviceToDevice);

    const long DD = (long)Dm * Dm;

    // -------- encoder stacks --------
    for (int i = 0; i < Ll; i++) {
        // x = attn(x, x) -> gh
        run_attn(gx, gx, enc_wq + i*DD, enc_wk + i*DD, enc_wv + i*DD,
                 gx, gh, gq, gk, gv, gs, ga);
        // x = LN(silu(gh @ fw + fb) + gh, g, b) -> gx
        launch_gemm(gh, enc_fw + i*DD, enc_fb + i*Dm, gt, ROWS, Dm, Dm, 1.f, 1, 0, 0, 0, false);
        addln_kernel<true, true><<<ROWS, 128>>>(gt, gh, enc_g + i*Dm, enc_b + i*Dm, gx);
    }

    // -------- decoder stacks --------
    for (int i = 0; i < Ll; i++) {
        // h = self-attn on encoder output x -> gh
        run_attn(gx, gx, dec_swq + i*DD, dec_swk + i*DD, dec_swv + i*DD,
                 gx, gh, gq, gk, gv, gs, ga);
        // h = cross-attn: q from h, k/v from decoder state out -> gh2
        run_attn(gh, gout, dec_cwq + i*DD, dec_cwk + i*DD, dec_cwv + i*DD,
                 gh, gh2, gq, gk, gv, gs, ga);
        // out = LN(silu(h2 @ fw + fb) + h2, g, b) -> gout
        launch_gemm(gh2, dec_fw + i*DD, dec_fb + i*Dm, gt, ROWS, Dm, Dm, 1.f, 1, 0, 0, 0, false);
        addln_kernel<true, true><<<ROWS, 128>>>(gt, gh2, dec_g + i*Dm, dec_b + i*Dm, gout);
    }

    // -------- vocab head + softmax --------
    float* logits = (float*)d_out;
    launch_gemm(gout, fc_w, nullptr, logits, ROWS, Vv, Dm, 1.f, 1, 0, 0, 0, false);
    softmax_kernel<<<ROWS, 512>>>(logits, Vv);
}

// round 3
// speedup vs baseline: 1.7306x; 1.7306x over previous
#include <cuda_runtime.h>
#include <cuda_bf16.h>
#include <math.h>
#include <stdint.h>

// Problem constants
#define Bsz 2
#define Sq  2048
#define Dm  512
#define Vv  32000
#define Ll  3
#define ROWS (Bsz*Sq)      // 4096
#define BD   (ROWS*Dm)     // 2097152 floats
#define SSZ  (Bsz*Sq*Sq)   // 8388608 floats
#define INV_SCALE 0.125f

// ---------------- fp32 scratch ----------------
__device__ float g_x[BD];
__device__ float g_out[BD];
__device__ float g_h[BD];
__device__ float g_h2[BD];
__device__ float g_q[BD];
__device__ float g_k[BD];
__device__ float g_v[BD];
__device__ float g_t[BD];
__device__ float g_a[BD];
__device__ float g_s[SSZ];

// ---------------- bf16 split scratch ----------------
__device__ __nv_bfloat16 sx_h[BD], sx_l[BD];
__device__ __nv_bfloat16 sy_h[BD], sy_l[BD];
__device__ __nv_bfloat16 sq_h[BD], sq_l[BD];
__device__ __nv_bfloat16 sk_h[BD], sk_l[BD];
__device__ __nv_bfloat16 svt_h[BD], svt_l[BD];
__device__ __nv_bfloat16 sp_h[SSZ], sp_l[SSZ];
__device__ __nv_bfloat16 sw_h[(long)Vv*Dm], sw_l[(long)Vv*Dm];

// ================= helpers =================
__device__ __forceinline__ uint32_t smem_u32(const void* p) {
    uint32_t a;
    asm("{ .reg .u64 t; cvta.to.shared.u64 t, %1; cvt.u32.u64 %0, t; }" : "=r"(a) : "l"(p));
    return a;
}

#define CP_ASYNC(dst, src) asm volatile("cp.async.ca.shared.global [%0], [%1], 16;" :: "r"(dst), "l"(src) : "memory")
#define CP_COMMIT()        asm volatile("cp.async.commit_group;" ::: "memory")
#define CP_WAIT(n)         asm volatile("cp.async.wait_group %0;" :: "n"(n) : "memory")

__device__ __forceinline__ void ldmx4(uint32_t& r0, uint32_t& r1, uint32_t& r2, uint32_t& r3, uint32_t a) {
    asm volatile("ldmatrix.sync.aligned.m8n8.x4.shared.b16 {%0,%1,%2,%3}, [%4];"
                 : "=r"(r0), "=r"(r1), "=r"(r2), "=r"(r3) : "r"(a));
}

__device__ __forceinline__ void mma_bf16(float* d, const uint32_t* a, const uint32_t* b) {
    asm volatile(
        "mma.sync.aligned.m16n8k16.row.col.f32.bf16.bf16.f32 "
        "{%0,%1,%2,%3}, {%4,%5,%6,%7}, {%8,%9}, {%0,%1,%2,%3};"
        : "+f"(d[0]), "+f"(d[1]), "+f"(d[2]), "+f"(d[3])
        : "r"(a[0]), "r"(a[1]), "r"(a[2]), "r"(a[3]), "r"(b[0]), "r"(b[1]));
}

// SMEM layout for a 128x32(bf16) tile, 8KB:
// logical (row r 0..127, half-index k 0..31) -> pairs of rows folded into one
// 128B physical row of 8 16B chunks, XOR-swizzled so ldmatrix (8 rows, fixed
// chunk) and cp.async stores are both bank-conflict-free.
__device__ __forceinline__ uint32_t sw_off(int r, int kc) {  // kc = k>>3 (0..3)
    const int pr = r >> 1;
    const int c8 = (kc | ((r & 1) << 2)) ^ (pr & 7);
    return (uint32_t)(pr * 128 + c8 * 16);
}

// ================= GEMM: C = alpha * A @ B^T (+bias), bf16x3 via mma.sync ====
// A: [M,K] bf16 hi/lo row-major; B: [N,K] bf16 hi/lo row-major; C fp32 [M,N].
// M%128==0, N%128==0, K%32==0. grid (N/128, M/128, batch), 256 threads.
#define TILE_B 8192
#define BUF_B  32768
#define GEMM_SMEM (2*BUF_B)

template<bool HAS_BIAS>
__global__ void __launch_bounds__(256, 1) gemm_mma3(
    const __nv_bfloat16* __restrict__ Ah, const __nv_bfloat16* __restrict__ Al,
    const __nv_bfloat16* __restrict__ Bh, const __nv_bfloat16* __restrict__ Bl,
    const float* __restrict__ bias, float* __restrict__ C,
    int M, int N, int K, float alpha,
    long sA, long sB, long sC)
{
    extern __shared__ char smem[];
    const uint32_t sb = smem_u32(smem);
    const int tid = threadIdx.x;
    const int wid = tid >> 5, lane = tid & 31;
    const int wm = wid >> 1, wn = wid & 1;          // warps: 4 (M) x 2 (N)
    const int bz = blockIdx.z;
    Ah += (long)bz * sA;  Al += (long)bz * sA;
    Bh += (long)bz * sB;  Bl += (long)bz * sB;
    C  += (long)bz * sC;

    const long rA0 = (long)blockIdx.y * 128;
    const long rB0 = (long)blockIdx.x * 128;

    // loader coords: 16B chunk per thread; 512 chunks per sub-tile, 2 per thread
    const int lr = tid >> 2;     // 0..63
    const int lc = tid & 3;      // chunk 0..3

    float acc[2][8][4];
    #pragma unroll
    for (int i = 0; i < 2; i++)
        #pragma unroll
        for (int j = 0; j < 8; j++)
            #pragma unroll
            for (int q = 0; q < 4; q++) acc[i][j][q] = 0.f;

    const int nk = K >> 5;

    auto load_tile = [&](int buf, int k0) {
        const uint32_t s0 = sb + buf * BUF_B;
        #pragma unroll
        for (int i = 0; i < 2; i++) {
            const int r = lr + i * 64;
            const uint32_t so = sw_off(r, lc);
            const long gofs = (long)r * K + k0 + lc * 8;
            CP_ASYNC(s0 + 0*TILE_B + so, Ah + rA0 * K + gofs);
            CP_ASYNC(s0 + 1*TILE_B + so, Al + rA0 * K + gofs);
            CP_ASYNC(s0 + 2*TILE_B + so, Bh + rB0 * K + gofs);
            CP_ASYNC(s0 + 3*TILE_B + so, Bl + rB0 * K + gofs);
        }
    };

    load_tile(0, 0);
    CP_COMMIT();

    for (int kt = 0; kt < nk; kt++) {
        if (kt + 1 < nk) {
            load_tile((kt + 1) & 1, (kt + 1) << 5);
            CP_COMMIT();
            CP_WAIT(1);
        } else {
            CP_WAIT(0);
        }
        __syncthreads();

        const uint32_t s0  = sb + (kt & 1) * BUF_B;
        const uint32_t sAH = s0, sAL = s0 + TILE_B, sBH = s0 + 2*TILE_B, sBL = s0 + 3*TILE_B;

        #pragma unroll
        for (int ks = 0; ks < 2; ks++) {
            const int kc0 = ks * 2;
            // A fragments: rows wm*32 + (lane&15) (+16 for mi=1), chunk kc0 + (lane>>4)
            uint32_t ah[2][4], al[2][4];
            const int arow = wm * 32 + (lane & 15);
            const int achk = kc0 + (lane >> 4);
            #pragma unroll
            for (int mi = 0; mi < 2; mi++) {
                const uint32_t off = sw_off(arow + mi * 16, achk);
                ldmx4(ah[mi][0], ah[mi][1], ah[mi][2], ah[mi][3], sAH + off);
                ldmx4(al[mi][0], al[mi][1], al[mi][2], al[mi][3], sAL + off);
            }
            // B fragments: rows wn*64 + nj*16 + ((lane>>4)<<3) + (lane&7),
            //              chunk kc0 + ((lane>>3)&1)
            uint32_t bh[8][2], bl[8][2];
            const int brow = wn * 64 + ((lane >> 4) << 3) + (lane & 7);
            const int bchk = kc0 + ((lane >> 3) & 1);
            #pragma unroll
            for (int nj = 0; nj < 4; nj++) {
                const uint32_t off = sw_off(brow + nj * 16, bchk);
                uint32_t t0, t1, t2, t3;
                ldmx4(t0, t1, t2, t3, sBH + off);
                bh[2*nj][0] = t0; bh[2*nj][1] = t1; bh[2*nj+1][0] = t2; bh[2*nj+1][1] = t3;
                ldmx4(t0, t1, t2, t3, sBL + off);
                bl[2*nj][0] = t0; bl[2*nj][1] = t1; bl[2*nj+1][0] = t2; bl[2*nj+1][1] = t3;
            }
            #pragma unroll
            for (int mi = 0; mi < 2; mi++)
                #pragma unroll
                for (int ni = 0; ni < 8; ni++) {
                    mma_bf16(acc[mi][ni], ah[mi], bh[ni]);
                    mma_bf16(acc[mi][ni], ah[mi], bl[ni]);
                    mma_bf16(acc[mi][ni], al[mi], bh[ni]);
                }
        }
        __syncthreads();
    }

    // epilogue
    const long rbase = rA0 + wm * 32 + (lane >> 2);
    const int  cbase = blockIdx.x * 128 + wn * 64 + (lane & 3) * 2;
    #pragma unroll
    for (int mi = 0; mi < 2; mi++) {
        #pragma unroll
        for (int ni = 0; ni < 8; ni++) {
            const int cc = cbase + ni * 8;
            float2 v0, v1;
            v0.x = alpha * acc[mi][ni][0];
            v0.y = alpha * acc[mi][ni][1];
            v1.x = alpha * acc[mi][ni][2];
            v1.y = alpha * acc[mi][ni][3];
            if (HAS_BIAS) {
                v0.x += bias[cc]; v0.y += bias[cc + 1];
                v1.x += bias[cc]; v1.y += bias[cc + 1];
            }
            const long r0 = rbase + mi * 16;
            *(float2*)(C + r0 * N + cc)       = v0;
            *(float2*)(C + (r0 + 8) * N + cc) = v1;
        }
    }
}

// ================= conversion kernels =================
__device__ __forceinline__ void split1(float x, __nv_bfloat16& h, __nv_bfloat16& l) {
    h = __float2bfloat16(x);
    l = __float2bfloat16(x - __bfloat162float(h));
}

__global__ void convsplit(const float* __restrict__ in,
                          __nv_bfloat16* __restrict__ oh, __nv_bfloat16* __restrict__ ol, long n)
{
    long i = ((long)blockIdx.x * blockDim.x + threadIdx.x) * 4;
    if (i >= n) return;
    float4 v = *(const float4*)(in + i);
    __nv_bfloat16 h0, h1, h2, h3, l0, l1, l2, l3;
    split1(v.x, h0, l0); split1(v.y, h1, l1); split1(v.z, h2, l2); split1(v.w, h3, l3);
    __nv_bfloat162 hh0 = {h0, h1}, hh1 = {h2, h3}, ll0 = {l0, l1}, ll1 = {l2, l3};
    *(uint2*)(oh + i) = make_uint2(*(uint32_t*)&hh0, *(uint32_t*)&hh1);
    *(uint2*)(ol + i) = make_uint2(*(uint32_t*)&ll0, *(uint32_t*)&ll1);
}

// transpose + split: in fp32 [R, C], out bf16 [C, R] (hi/lo). grid (C/32, R/32, batch)
__global__ void __launch_bounds__(256) tconvsplit(
    const float* __restrict__ in, __nv_bfloat16* __restrict__ oh, __nv_bfloat16* __restrict__ ol,
    int R, int C, long sIn, long sOut)
{
    __shared__ float t[32][33];
    in += (long)blockIdx.z * sIn;
    oh += (long)blockIdx.z * sOut;
    ol += (long)blockIdx.z * sOut;
    const int c0 = blockIdx.x * 32, r0 = blockIdx.y * 32;
    const int tx = threadIdx.x, ty = threadIdx.y;  // (32, 8)
    #pragma unroll
    for (int j = 0; j < 32; j += 8)
        t[ty + j][tx] = in[(long)(r0 + ty + j) * C + c0 + tx];
    __syncthreads();
    #pragma unroll
    for (int j = 0; j < 32; j += 8) {
        float v = t[tx][ty + j];
        __nv_bfloat16 h, l;
        split1(v, h, l);
        long o = (long)(c0 + ty + j) * R + r0 + tx;
        oh[o] = h; ol[o] = l;
    }
}

// ================= reductions / softmax / layernorm =================
__device__ __forceinline__ float blockReduceMax(float v, float* sh) {
    const int lane = threadIdx.x & 31, w = threadIdx.x >> 5;
    #pragma unroll
    for (int o = 16; o; o >>= 1) v = fmaxf(v, __shfl_xor_sync(0xffffffffu, v, o));
    if (lane == 0) sh[w] = v;
    __syncthreads();
    const int nw = (blockDim.x + 31) >> 5;
    if (w == 0) {
        float t = (lane < nw) ? sh[lane] : -INFINITY;
        #pragma unroll
        for (int o = 16; o; o >>= 1) t = fmaxf(t, __shfl_xor_sync(0xffffffffu, t, o));
        if (lane == 0) sh[0] = t;
    }
    __syncthreads();
    float r = sh[0];
    __syncthreads();
    return r;
}
__device__ __forceinline__ float blockReduceSum(float v, float* sh) {
    const int lane = threadIdx.x & 31, w = threadIdx.x >> 5;
    #pragma unroll
    for (int o = 16; o; o >>= 1) v += __shfl_xor_sync(0xffffffffu, v, o);
    if (lane == 0) sh[w] = v;
    __syncthreads();
    const int nw = (blockDim.x + 31) >> 5;
    if (w == 0) {
        float t = (lane < nw) ? sh[lane] : 0.f;
        #pragma unroll
        for (int o = 16; o; o >>= 1) t += __shfl_xor_sync(0xffffffffu, t, o);
        if (lane == 0) sh[0] = t;
    }
    __syncthreads();
    float r = sh[0];
    __syncthreads();
    return r;
}

__global__ void softmax_kernel(float* __restrict__ data, int N) {
    __shared__ float sh[32];
    float* row = data + (size_t)blockIdx.x * N;
    float m = -INFINITY;
    for (int i = threadIdx.x; i < N; i += blockDim.x) m = fmaxf(m, row[i]);
    m = blockReduceMax(m, sh);
    float s = 0.f;
    for (int i = threadIdx.x; i < N; i += blockDim.x) s += __expf(row[i] - m);
    s = blockReduceSum(s, sh);
    const float inv = 1.f / s;
    for (int i = threadIdx.x; i < N; i += blockDim.x) row[i] = __expf(row[i] - m) * inv;
}

__global__ void softmax_split_kernel(const float* __restrict__ in,
                                     __nv_bfloat16* __restrict__ oh, __nv_bfloat16* __restrict__ ol, int N)
{
    __shared__ float sh[32];
    const float* row = in + (size_t)blockIdx.x * N;
    float m = -INFINITY;
    for (int i = threadIdx.x; i < N; i += blockDim.x) m = fmaxf(m, row[i]);
    m = blockReduceMax(m, sh);
    float s = 0.f;
    for (int i = threadIdx.x; i < N; i += blockDim.x) s += __expf(row[i] - m);
    s = blockReduceSum(s, sh);
    const float inv = 1.f / s;
    const size_t base = (size_t)blockIdx.x * N;
    for (int i = threadIdx.x; i < N; i += blockDim.x) {
        float p = __expf(row[i] - m) * inv;
        __nv_bfloat16 h, l;
        split1(p, h, l);
        oh[base + i] = h; ol[base + i] = l;
    }
}

template<bool SILU, bool AFFINE>
__global__ void __launch_bounds__(128) addln_kernel(
    const float* __restrict__ a, const float* __restrict__ res,
    const float* __restrict__ g, const float* __restrict__ bta,
    float* __restrict__ out)
{
    const int row = blockIdx.x;
    const int tid = threadIdx.x;
    float4 av = ((const float4*)(a   + (size_t)row * Dm))[tid];
    float4 rv = ((const float4*)(res + (size_t)row * Dm))[tid];
    float v[4] = {av.x, av.y, av.z, av.w};
    float r[4] = {rv.x, rv.y, rv.z, rv.w};

    float s = 0.f, s2 = 0.f;
    #pragma unroll
    for (int i = 0; i < 4; i++) {
        float t = SILU ? (v[i] / (1.f + __expf(-v[i]))) : v[i];
        t += r[i];
        v[i] = t;
        s += t; s2 += t * t;
    }
    __shared__ float ss[4], ss2[4];
    #pragma unroll
    for (int o = 16; o; o >>= 1) {
        s  += __shfl_xor_sync(0xffffffffu, s,  o);
        s2 += __shfl_xor_sync(0xffffffffu, s2, o);
    }
    const int w = tid >> 5, lane = tid & 31;
    if (lane == 0) { ss[w] = s; ss2[w] = s2; }
    __syncthreads();
    s  = ss[0]  + ss[1]  + ss[2]  + ss[3];
    s2 = ss2[0] + ss2[1] + ss2[2] + ss2[3];

    const float mean = s * (1.f / Dm);
    const float var  = s2 * (1.f / Dm) - mean * mean;
    const float inv  = rsqrtf(var + 1e-5f);

    float ov[4];
    #pragma unroll
    for (int i = 0; i < 4; i++) {
        float yv = (v[i] - mean) * inv;
        if (AFFINE) {
            const int c = tid * 4 + i;
            yv = yv * g[c] + bta[c];
        }
        ov[i] = yv;
    }
    float4 o4 = {ov[0], ov[1], ov[2], ov[3]};
    ((float4*)(out + (size_t)row * Dm))[tid] = o4;
}

// ================= host-side orchestration =================
struct Ptrs {
    float *gx, *gout, *gh, *gh2, *gq, *gk, *gv, *gt, *ga, *gs;
    __nv_bfloat16 *xh, *xl, *yh, *yl, *qh, *ql, *kh, *kl, *vth, *vtl, *ph, *pl, *wh, *wl;
};

static void launch_gemm3(const __nv_bfloat16* Ah, const __nv_bfloat16* Al,
                         const __nv_bfloat16* Bh, const __nv_bfloat16* Bl,
                         const float* bias, float* C,
                         int M, int N, int K, float alpha, int batch,
                         long sA, long sB, long sC)
{
    dim3 grid(N / 128, M / 128, batch), block(256);
    if (bias) gemm_mma3<true ><<<grid, block, GEMM_SMEM>>>(Ah, Al, Bh, Bl, bias, C, M, N, K, alpha, sA, sB, sC);
    else      gemm_mma3<false><<<grid, block, GEMM_SMEM>>>(Ah, Al, Bh, Bl, bias, C, M, N, K, alpha, sA, sB, sC);
}

static void conv(const float* in, __nv_bfloat16* oh, __nv_bfloat16* ol, long n) {
    convsplit<<<(unsigned)((n / 4 + 255) / 256), 256>>>(in, oh, ol, n);
}
static void tconv(const float* in, __nv_bfloat16* oh, __nv_bfloat16* ol,
                  int R, int C, int batch, long sIn, long sOut) {
    dim3 grid(C / 32, R / 32, batch), block(32, 8);
    tconvsplit<<<grid, block>>>(in, oh, ol, R, C, sIn, sOut);
}

static void run_attn(const Ptrs& P, const float* qsrc, const float* ctx,
                     const float* wq, const float* wk, const float* wv,
                     const float* resid, float* outp)
{
    const __nv_bfloat16 *ch, *cl;
    conv(qsrc, P.xh, P.xl, BD);
    if (ctx == qsrc) { ch = P.xh; cl = P.xl; }
    else { conv(ctx, P.yh, P.yl, BD); ch = P.yh; cl = P.yl; }

    tconv(wq, P.wh, P.wl, Dm, Dm, 1, 0, 0);
    launch_gemm3(P.xh, P.xl, P.wh, P.wl, nullptr, P.gq, ROWS, Dm, Dm, 1.f, 1, 0, 0, 0);
    tconv(wk, P.wh, P.wl, Dm, Dm, 1, 0, 0);
    launch_gemm3(ch, cl, P.wh, P.wl, nullptr, P.gk, ROWS, Dm, Dm, 1.f, 1, 0, 0, 0);
    tconv(wv, P.wh, P.wl, Dm, Dm, 1, 0, 0);
    launch_gemm3(ch, cl, P.wh, P.wl, nullptr, P.gv, ROWS, Dm, Dm, 1.f, 1, 0, 0, 0);

    conv(P.gq, P.qh, P.ql, BD);
    conv(P.gk, P.kh, P.kl, BD);
    launch_gemm3(P.qh, P.ql, P.kh, P.kl, nullptr, P.gs, Sq, Sq, Dm, INV_SCALE, Bsz,
                 (long)Sq * Dm, (long)Sq * Dm, (long)Sq * Sq);
    softmax_split_kernel<<<ROWS, 256>>>(P.gs, P.ph, P.pl, Sq);
    tconv(P.gv, P.vth, P.vtl, Sq, Dm, Bsz, (long)Sq * Dm, (long)Sq * Dm);
    launch_gemm3(P.ph, P.pl, P.vth, P.vtl, nullptr, P.ga, Sq, Dm, Sq, 1.f, Bsz,
                 (long)Sq * Sq, (long)Sq * Dm, (long)Sq * Dm);
    addln_kernel<false, false><<<ROWS, 128>>>(P.ga, resid, nullptr, nullptr, outp);
}

extern "C" void kernel_launch(void* const* d_in, const int* in_sizes, int n_in,
                              void* d_out, int out_size)
{
    const float* x       = (const float*)d_in[0];
    const float* y       = (const float*)d_in[1];
    const float* enc_wq  = (const float*)d_in[2];
    const float* enc_wk  = (const float*)d_in[3];
    const float* enc_wv  = (const float*)d_in[4];
    const float* enc_fw  = (const float*)d_in[5];
    const float* enc_fb  = (const float*)d_in[6];
    const float* enc_g   = (const float*)d_in[7];
    const float* enc_b   = (const float*)d_in[8];
    const float* dec_swq = (const float*)d_in[9];
    const float* dec_swk = (const float*)d_in[10];
    const float* dec_swv = (const float*)d_in[11];
    const float* dec_cwq = (const float*)d_in[12];
    const float* dec_cwk = (const float*)d_in[13];
    const float* dec_cwv = (const float*)d_in[14];
    const float* dec_fw  = (const float*)d_in[15];
    const float* dec_fb  = (const float*)d_in[16];
    const float* dec_g   = (const float*)d_in[17];
    const float* dec_b   = (const float*)d_in[18];
    const float* fc_w    = (const float*)d_in[19];

    cudaFuncSetAttribute(gemm_mma3<true >, cudaFuncAttributeMaxDynamicSharedMemorySize, GEMM_SMEM);
    cudaFuncSetAttribute(gemm_mma3<false>, cudaFuncAttributeMaxDynamicSharedMemorySize, GEMM_SMEM);

    Ptrs P;
    cudaGetSymbolAddress((void**)&P.gx,   g_x);
    cudaGetSymbolAddress((void**)&P.gout, g_out);
    cudaGetSymbolAddress((void**)&P.gh,   g_h);
    cudaGetSymbolAddress((void**)&P.gh2,  g_h2);
    cudaGetSymbolAddress((void**)&P.gq,   g_q);
    cudaGetSymbolAddress((void**)&P.gk,   g_k);
    cudaGetSymbolAddress((void**)&P.gv,   g_v);
    cudaGetSymbolAddress((void**)&P.gt,   g_t);
    cudaGetSymbolAddress((void**)&P.ga,   g_a);
    cudaGetSymbolAddress((void**)&P.gs,   g_s);
    cudaGetSymbolAddress((void**)&P.xh,  sx_h);  cudaGetSymbolAddress((void**)&P.xl,  sx_l);
    cudaGetSymbolAddress((void**)&P.yh,  sy_h);  cudaGetSymbolAddress((void**)&P.yl,  sy_l);
    cudaGetSymbolAddress((void**)&P.qh,  sq_h);  cudaGetSymbolAddress((void**)&P.ql,  sq_l);
    cudaGetSymbolAddress((void**)&P.kh,  sk_h);  cudaGetSymbolAddress((void**)&P.kl,  sk_l);
    cudaGetSymbolAddress((void**)&P.vth, svt_h); cudaGetSymbolAddress((void**)&P.vtl, svt_l);
    cudaGetSymbolAddress((void**)&P.ph,  sp_h);  cudaGetSymbolAddress((void**)&P.pl,  sp_l);
    cudaGetSymbolAddress((void**)&P.wh,  sw_h);  cudaGetSymbolAddress((void**)&P.wl,  sw_l);

    cudaMemcpyAsync(P.gx,   x, (size_t)BD * sizeof(float), cudaMemcpyDeviceToDevice);
    cudaMemcpyAsync(P.gout, y, (size_t)BD * sizeof(float), cudaMemcpyDeviceToDevice);

    const long DD = (long)Dm * Dm;

    // -------- encoder stacks --------
    for (int i = 0; i < Ll; i++) {
        run_attn(P, P.gx, P.gx, enc_wq + i * DD, enc_wk + i * DD, enc_wv + i * DD, P.gx, P.gh);
        conv(P.gh, P.xh, P.xl, BD);
        tconv(enc_fw + i * DD, P.wh, P.wl, Dm, Dm, 1, 0, 0);
        launch_gemm3(P.xh, P.xl, P.wh, P.wl, enc_fb + i * Dm, P.gt, ROWS, Dm, Dm, 1.f, 1, 0, 0, 0);
        addln_kernel<true, true><<<ROWS, 128>>>(P.gt, P.gh, enc_g + i * Dm, enc_b + i * Dm, P.gx);
    }

    // -------- decoder stacks --------
    for (int i = 0; i < Ll; i++) {
        run_attn(P, P.gx, P.gx, dec_swq + i * DD, dec_swk + i * DD, dec_swv + i * DD, P.gx, P.gh);
        run_attn(P, P.gh, P.gout, dec_cwq + i * DD, dec_cwk + i * DD, dec_cwv + i * DD, P.gh, P.gh2);
        conv(P.gh2, P.xh, P.xl, BD);
        tconv(dec_fw + i * DD, P.wh, P.wl, Dm, Dm, 1, 0, 0);
        launch_gemm3(P.xh, P.xl, P.wh, P.wl, dec_fb + i * Dm, P.gt, ROWS, Dm, Dm, 1.f, 1, 0, 0, 0);
        addln_kernel<true, true><<<ROWS, 128>>>(P.gt, P.gh2, dec_g + i * Dm, dec_b + i * Dm, P.gout);
    }

    // -------- vocab head + softmax --------
    conv(P.gout, P.xh, P.xl, BD);
    tconv(fc_w, P.wh, P.wl, Dm, Vv, 1, 0, 0);
    float* logits = (float*)d_out;
    launch_gemm3(P.xh, P.xl, P.wh, P.wl, nullptr, logits, ROWS, Vv, Dm, 1.f, 1, 0, 0, 0);
    softmax_kernel<<<ROWS, 512>>>(logits, Vv);
}

// round 4
// speedup vs baseline: 2.9876x; 1.7263x over previous
#include <cuda_runtime.h>
#include <cuda_bf16.h>
#include <math.h>
#include <stdint.h>

// Problem constants
#define Bsz 2
#define Sq  2048
#define Dm  512
#define Vv  32000
#define Ll  3
#define ROWS (Bsz*Sq)      // 4096
#define BD   (ROWS*Dm)     // 2097152
#define SSZ  (Bsz*Sq*Sq)   // 8388608
#define INV_SCALE 0.125f

// ---------------- fp32 scratch ----------------
__device__ float g_x[BD];
__device__ float g_out[BD];
__device__ float g_h[BD];
__device__ float g_h2[BD];
__device__ float g_t[BD];
__device__ float g_a[BD];
__device__ float g_s[SSZ];

// ---------------- bf16 split scratch ----------------
__device__ __nv_bfloat16 sx_h[BD],  sx_l[BD];     // enc state split
__device__ __nv_bfloat16 so_h[BD],  so_l[BD];     // dec state split
__device__ __nv_bfloat16 sh_h[BD],  sh_l[BD];     // attn-out split
__device__ __nv_bfloat16 sh2_h[BD], sh2_l[BD];    // attn2-out split
__device__ __nv_bfloat16 sq_h[BD],  sq_l[BD];
__device__ __nv_bfloat16 sk_h[BD],  sk_l[BD];
__device__ __nv_bfloat16 sv_h[BD],  sv_l[BD];
__device__ __nv_bfloat16 svt_h[BD], svt_l[BD];
__device__ __nv_bfloat16 sp_h[SSZ], sp_l[SSZ];
__device__ __nv_bfloat16 sw_h[(long)Vv*Dm], sw_l[(long)Vv*Dm];

// ================= helpers =================
__device__ __forceinline__ uint32_t smem_u32(const void* p) {
    uint32_t a;
    asm("{ .reg .u64 t; cvta.to.shared.u64 t, %1; cvt.u32.u64 %0, t; }" : "=r"(a) : "l"(p));
    return a;
}
#define CP_ASYNC(dst, src) asm volatile("cp.async.ca.shared.global [%0], [%1], 16;" :: "r"(dst), "l"(src) : "memory")
#define CP_COMMIT()        asm volatile("cp.async.commit_group;" ::: "memory")
#define CP_WAIT(n)         asm volatile("cp.async.wait_group %0;" :: "n"(n) : "memory")

__device__ __forceinline__ void ldmx4(uint32_t& r0, uint32_t& r1, uint32_t& r2, uint32_t& r3, uint32_t a) {
    asm volatile("ldmatrix.sync.aligned.m8n8.x4.shared.b16 {%0,%1,%2,%3}, [%4];"
                 : "=r"(r0), "=r"(r1), "=r"(r2), "=r"(r3) : "r"(a));
}
__device__ __forceinline__ void mma_bf16(float* d, const uint32_t* a, const uint32_t* b) {
    asm volatile(
        "mma.sync.aligned.m16n8k16.row.col.f32.bf16.bf16.f32 "
        "{%0,%1,%2,%3}, {%4,%5,%6,%7}, {%8,%9}, {%0,%1,%2,%3};"
        : "+f"(d[0]), "+f"(d[1]), "+f"(d[2]), "+f"(d[3])
        : "r"(a[0]), "r"(a[1]), "r"(a[2]), "r"(a[3]), "r"(b[0]), "r"(b[1]));
}
__device__ __forceinline__ void split1(float x, __nv_bfloat16& h, __nv_bfloat16& l) {
    h = __float2bfloat16(x);
    l = __float2bfloat16(x - __bfloat162float(h));
}

// SW128 swizzle for a 128-row x 64-bf16 (128B/row) tile. c = 16B chunk 0..7.
__device__ __forceinline__ uint32_t swz(int r, int c) {
    return (uint32_t)(r * 128 + ((c ^ (r & 7)) * 16));
}

// ================= GEMM: C = alpha * A @ B^T (+bias | split out) ============
// A: [M,K] bf16 hi/lo; B: [N,K] bf16 hi/lo. bf16x3: Ah*Bh + Ah*Bl + Al*Bh.
// BM=BN=128, BK=64, 512 threads (16 warps: 8 M x 2 N, warp tile 16x64),
// 3-stage cp.async pipeline, 192KB dynamic smem.
#define TILEB 16384
#define STAGEB (4*TILEB)
#define GEMM_SMEM (3*STAGEB)

template<bool HAS_BIAS, bool SPLIT>
__global__ void __launch_bounds__(512, 1) gemm3(
    const __nv_bfloat16* __restrict__ Ah, const __nv_bfloat16* __restrict__ Al,
    const __nv_bfloat16* __restrict__ Bh, const __nv_bfloat16* __restrict__ Bl,
    const float* __restrict__ bias,
    float* __restrict__ C, __nv_bfloat16* __restrict__ Ch, __nv_bfloat16* __restrict__ Cl,
    int M, int N, int K, float alpha, long sA, long sB, long sC)
{
    extern __shared__ char smem[];
    const uint32_t sb = smem_u32(smem);
    const int tid = threadIdx.x, lane = tid & 31, wid = tid >> 5;
    const int wm = wid >> 1, wn = wid & 1;
    const int bz = blockIdx.z;
    Ah += (long)bz * sA;  Al += (long)bz * sA;
    Bh += (long)bz * sB;  Bl += (long)bz * sB;

    const long rA0 = (long)blockIdx.y * 128;
    const long rB0 = (long)blockIdx.x * 128;

    // loader: 1024 16B-chunks per 16KB subtile; 512 threads x 2 chunks
    const int q0 = tid, q1 = tid + 512;
    const int r0l = q0 >> 3, c0l = q0 & 7;
    const int r1l = q1 >> 3, c1l = q1 & 7;
    const uint32_t so0 = swz(r0l, c0l), so1 = swz(r1l, c1l);
    const __nv_bfloat16* gAh = Ah + rA0 * K;
    const __nv_bfloat16* gAl = Al + rA0 * K;
    const __nv_bfloat16* gBh = Bh + rB0 * K;
    const __nv_bfloat16* gBl = Bl + rB0 * K;
    const long go0 = (long)r0l * K + c0l * 8;
    const long go1 = (long)r1l * K + c1l * 8;

    float acc[8][4];
    #pragma unroll
    for (int i = 0; i < 8; i++)
        #pragma unroll
        for (int q = 0; q < 4; q++) acc[i][q] = 0.f;

    const int nk = K >> 6;

    auto load_tile = [&](int st, int k0) {
        const uint32_t s = sb + st * STAGEB;
        CP_ASYNC(s + 0*TILEB + so0, gAh + go0 + k0);
        CP_ASYNC(s + 0*TILEB + so1, gAh + go1 + k0);
        CP_ASYNC(s + 1*TILEB + so0, gAl + go0 + k0);
        CP_ASYNC(s + 1*TILEB + so1, gAl + go1 + k0);
        CP_ASYNC(s + 2*TILEB + so0, gBh + go0 + k0);
        CP_ASYNC(s + 2*TILEB + so1, gBh + go1 + k0);
        CP_ASYNC(s + 3*TILEB + so0, gBl + go0 + k0);
        CP_ASYNC(s + 3*TILEB + so1, gBl + go1 + k0);
    };

    load_tile(0, 0);  CP_COMMIT();
    load_tile(1, 64); CP_COMMIT();

    int st = 0;
    for (int kt = 0; kt < nk; kt++) {
        if (kt + 1 < nk) { CP_WAIT(1); } else { CP_WAIT(0); }
        __syncthreads();
        if (kt + 2 < nk) {
            int st2 = st + 2; if (st2 >= 3) st2 -= 3;
            load_tile(st2, (kt + 2) << 6);
            CP_COMMIT();
        }

        const uint32_t s0  = sb + st * STAGEB;
        const uint32_t sAH = s0, sAL = s0 + TILEB, sBH = s0 + 2*TILEB, sBL = s0 + 3*TILEB;
        const int arow = wm * 16 + (lane & 15);
        const int brow = wn * 64 + ((lane >> 4) << 3) + (lane & 7);

        #pragma unroll
        for (int ks = 0; ks < 4; ks++) {
            const int achk = ks * 2 + (lane >> 4);
            const int bchk = ks * 2 + ((lane >> 3) & 1);
            uint32_t ah[4], al[4];
            {
                const uint32_t off = swz(arow, achk);
                ldmx4(ah[0], ah[1], ah[2], ah[3], sAH + off);
                ldmx4(al[0], al[1], al[2], al[3], sAL + off);
            }
            uint32_t bh[8][2], bl[8][2];
            #pragma unroll
            for (int nj = 0; nj < 4; nj++) {
                const uint32_t off = swz(brow + nj * 16, bchk);
                uint32_t t0, t1, t2, t3;
                ldmx4(t0, t1, t2, t3, sBH + off);
                bh[2*nj][0] = t0; bh[2*nj][1] = t1; bh[2*nj+1][0] = t2; bh[2*nj+1][1] = t3;
                ldmx4(t0, t1, t2, t3, sBL + off);
                bl[2*nj][0] = t0; bl[2*nj][1] = t1; bl[2*nj+1][0] = t2; bl[2*nj+1][1] = t3;
            }
            #pragma unroll
            for (int ni = 0; ni < 8; ni++) {
                mma_bf16(acc[ni], ah, bh[ni]);
                mma_bf16(acc[ni], ah, bl[ni]);
                mma_bf16(acc[ni], al, bh[ni]);
            }
        }
        st++; if (st >= 3) st = 0;
    }

    // epilogue
    const long rb  = rA0 + wm * 16 + (lane >> 2) + (long)bz * sC / 1;  // bz offset applied below
    const long rbase = rA0 + wm * 16 + (lane >> 2);
    (void)rb;
    const int  cbase = blockIdx.x * 128 + wn * 64 + (lane & 3) * 2;
    #pragma unroll
    for (int ni = 0; ni < 8; ni++) {
        const int cc = cbase + ni * 8;
        float v00 = alpha * acc[ni][0], v01 = alpha * acc[ni][1];
        float v10 = alpha * acc[ni][2], v11 = alpha * acc[ni][3];
        if (HAS_BIAS) {
            v00 += bias[cc]; v01 += bias[cc + 1];
            v10 += bias[cc]; v11 += bias[cc + 1];
        }
        const long r0 = (long)bz * sC + rbase * N;
        const long r1 = r0 + 8 * N;
        if (SPLIT) {
            __nv_bfloat16 h0, l0, h1, l1;
            split1(v00, h0, l0); split1(v01, h1, l1);
            *(__nv_bfloat162*)(Ch + r0 + cc) = {h0, h1};
            *(__nv_bfloat162*)(Cl + r0 + cc) = {l0, l1};
            split1(v10, h0, l0); split1(v11, h1, l1);
            *(__nv_bfloat162*)(Ch + r1 + cc) = {h0, h1};
            *(__nv_bfloat162*)(Cl + r1 + cc) = {l0, l1};
        } else {
            *(float2*)(C + r0 + cc) = {v00, v01};
            *(float2*)(C + r1 + cc) = {v10, v11};
        }
    }
}

// ================= conversion kernels =================
__global__ void convsplit(const float* __restrict__ in,
                          __nv_bfloat16* __restrict__ oh, __nv_bfloat16* __restrict__ ol, long n)
{
    long i = ((long)blockIdx.x * blockDim.x + threadIdx.x) * 4;
    if (i >= n) return;
    float4 v = *(const float4*)(in + i);
    __nv_bfloat16 h0, h1, h2, h3, l0, l1, l2, l3;
    split1(v.x, h0, l0); split1(v.y, h1, l1); split1(v.z, h2, l2); split1(v.w, h3, l3);
    __nv_bfloat162 hh0 = {h0, h1}, hh1 = {h2, h3}, ll0 = {l0, l1}, ll1 = {l2, l3};
    *(uint2*)(oh + i) = make_uint2(*(uint32_t*)&hh0, *(uint32_t*)&hh1);
    *(uint2*)(ol + i) = make_uint2(*(uint32_t*)&ll0, *(uint32_t*)&ll1);
}

// transpose + split: fp32 [R,C] -> bf16 hi/lo [C,R]
__global__ void __launch_bounds__(256) tconvsplit(
    const float* __restrict__ in, __nv_bfloat16* __restrict__ oh, __nv_bfloat16* __restrict__ ol,
    int R, int C)
{
    __shared__ float t[32][33];
    const int c0 = blockIdx.x * 32, r0 = blockIdx.y * 32;
    const int tx = threadIdx.x, ty = threadIdx.y;
    #pragma unroll
    for (int j = 0; j < 32; j += 8)
        t[ty + j][tx] = in[(long)(r0 + ty + j) * C + c0 + tx];
    __syncthreads();
    #pragma unroll
    for (int j = 0; j < 32; j += 8) {
        float v = t[tx][ty + j];
        __nv_bfloat16 h, l;
        split1(v, h, l);
        long o = (long)(c0 + ty + j) * R + r0 + tx;
        oh[o] = h; ol[o] = l;
    }
}

// bf16 pair transpose: [R,C] -> [C,R], batched
__global__ void __launch_bounds__(256) tbf16(
    const __nv_bfloat16* __restrict__ ih, const __nv_bfloat16* __restrict__ il,
    __nv_bfloat16* __restrict__ oh, __nv_bfloat16* __restrict__ ol,
    int R, int C, long sIO)
{
    __shared__ __nv_bfloat16 th[32][33], tl[32][33];
    ih += (long)blockIdx.z * sIO;  il += (long)blockIdx.z * sIO;
    oh += (long)blockIdx.z * sIO;  ol += (long)blockIdx.z * sIO;
    const int c0 = blockIdx.x * 32, r0 = blockIdx.y * 32;
    const int tx = threadIdx.x, ty = threadIdx.y;
    #pragma unroll
    for (int j = 0; j < 32; j += 8) {
        long idx = (long)(r0 + ty + j) * C + c0 + tx;
        th[ty + j][tx] = ih[idx];
        tl[ty + j][tx] = il[idx];
    }
    __syncthreads();
    #pragma unroll
    for (int j = 0; j < 32; j += 8) {
        long o = (long)(c0 + ty + j) * R + r0 + tx;
        oh[o] = th[tx][ty + j];
        ol[o] = tl[tx][ty + j];
    }
}

// ================= online softmax =================
__device__ __forceinline__ void sm_merge(float& m, float& s, float m2, float s2) {
    float M = fmaxf(m, m2);
    s = s * __expf(m - M) + s2 * __expf(m2 - M);
    m = M;
}

__device__ __forceinline__ void block_softmax_stats(float& m, float& s) {
    __shared__ float shm[32], shs[32];
    const int lane = threadIdx.x & 31, w = threadIdx.x >> 5;
    #pragma unroll
    for (int o = 16; o; o >>= 1)
        sm_merge(m, s, __shfl_xor_sync(0xffffffffu, m, o), __shfl_xor_sync(0xffffffffu, s, o));
    if (lane == 0) { shm[w] = m; shs[w] = s; }
    __syncthreads();
    const int nw = blockDim.x >> 5;
    if (w == 0) {
        float mm = (lane < nw) ? shm[lane] : -1e30f;
        float ss = (lane < nw) ? shs[lane] : 0.f;
        #pragma unroll
        for (int o = 16; o; o >>= 1)
            sm_merge(mm, ss, __shfl_xor_sync(0xffffffffu, mm, o), __shfl_xor_sync(0xffffffffu, ss, o));
        if (lane == 0) { shm[0] = mm; shs[0] = ss; }
    }
    __syncthreads();
    m = shm[0]; s = shs[0];
    __syncthreads();
}

__global__ void softmax_kernel(float* __restrict__ data, int N) {
    float* row = data + (size_t)blockIdx.x * N;
    float m = -1e30f, s = 0.f;
    for (int i = threadIdx.x; i < N; i += blockDim.x) {
        float v = row[i];
        float mo = m;
        m = fmaxf(m, v);
        s = s * __expf(mo - m) + __expf(v - m);
    }
    block_softmax_stats(m, s);
    const float inv = 1.f / s;
    for (int i = threadIdx.x; i < N; i += blockDim.x)
        row[i] = __expf(row[i] - m) * inv;
}

__global__ void softmax_split_kernel(const float* __restrict__ in,
                                     __nv_bfloat16* __restrict__ oh, __nv_bfloat16* __restrict__ ol, int N)
{
    const float* row = in + (size_t)blockIdx.x * N;
    float m = -1e30f, s = 0.f;
    for (int i = threadIdx.x; i < N; i += blockDim.x) {
        float v = row[i];
        float mo = m;
        m = fmaxf(m, v);
        s = s * __expf(mo - m) + __expf(v - m);
    }
    block_softmax_stats(m, s);
    const float inv = 1.f / s;
    const size_t base = (size_t)blockIdx.x * N;
    for (int i = threadIdx.x; i < N; i += blockDim.x) {
        float p = __expf(row[i] - m) * inv;
        __nv_bfloat16 h, l;
        split1(p, h, l);
        oh[base + i] = h; ol[base + i] = l;
    }
}

// ========== fused (silu?)+residual+LayerNorm, fp32 out + split out ==========
template<bool SILU, bool AFFINE>
__global__ void __launch_bounds__(128) addln_kernel(
    const float* __restrict__ a, const float* __restrict__ res,
    const float* __restrict__ g, const float* __restrict__ bta,
    float* __restrict__ out, __nv_bfloat16* __restrict__ oh, __nv_bfloat16* __restrict__ ol)
{
    const int row = blockIdx.x;
    const int tid = threadIdx.x;
    float4 av = ((const float4*)(a   + (size_t)row * Dm))[tid];
    float4 rv = ((const float4*)(res + (size_t)row * Dm))[tid];
    float v[4] = {av.x, av.y, av.z, av.w};
    float r[4] = {rv.x, rv.y, rv.z, rv.w};

    float s = 0.f, s2 = 0.f;
    #pragma unroll
    for (int i = 0; i < 4; i++) {
        float t = SILU ? (v[i] / (1.f + __expf(-v[i]))) : v[i];
        t += r[i];
        v[i] = t;
        s += t; s2 += t * t;
    }
    __shared__ float ss[4], ss2[4];
    #pragma unroll
    for (int o = 16; o; o >>= 1) {
        s  += __shfl_xor_sync(0xffffffffu, s,  o);
        s2 += __shfl_xor_sync(0xffffffffu, s2, o);
    }
    const int w = tid >> 5, lane = tid & 31;
    if (lane == 0) { ss[w] = s; ss2[w] = s2; }
    __syncthreads();
    s  = ss[0]  + ss[1]  + ss[2]  + ss[3];
    s2 = ss2[0] + ss2[1] + ss2[2] + ss2[3];

    const float mean = s * (1.f / Dm);
    const float var  = s2 * (1.f / Dm) - mean * mean;
    const float inv  = rsqrtf(var + 1e-5f);

    float ov[4];
    __nv_bfloat16 hh[4], ll[4];
    #pragma unroll
    for (int i = 0; i < 4; i++) {
        float yv = (v[i] - mean) * inv;
        if (AFFINE) {
            const int c = tid * 4 + i;
            yv = yv * g[c] + bta[c];
        }
        ov[i] = yv;
        split1(yv, hh[i], ll[i]);
    }
    float4 o4 = {ov[0], ov[1], ov[2], ov[3]};
    ((float4*)(out + (size_t)row * Dm))[tid] = o4;
    __nv_bfloat162 h0 = {hh[0], hh[1]}, h1 = {hh[2], hh[3]};
    __nv_bfloat162 l0 = {ll[0], ll[1]}, l1 = {ll[2], ll[3]};
    ((uint2*)(oh + (size_t)row * Dm))[tid] = make_uint2(*(uint32_t*)&h0, *(uint32_t*)&h1);
    ((uint2*)(ol + (size_t)row * Dm))[tid] = make_uint2(*(uint32_t*)&l0, *(uint32_t*)&l1);
}

// ================= host-side orchestration =================
struct Ptrs {
    float *gx, *gout, *gh, *gh2, *gt, *ga, *gs;
    __nv_bfloat16 *xh, *xl, *oh, *ol, *hh, *hl, *h2h, *h2l;
    __nv_bfloat16 *qh, *ql, *kh, *kl, *vh, *vl, *vth, *vtl, *ph, *pl, *wh, *wl;
};

static void G(const __nv_bfloat16* Ah, const __nv_bfloat16* Al,
              const __nv_bfloat16* Bh, const __nv_bfloat16* Bl,
              const float* bias, float* C, __nv_bfloat16* Ch, __nv_bfloat16* Cl,
              int M, int N, int K, float alpha, int batch,
              long sA, long sB, long sC)
{
    dim3 grid(N / 128, M / 128, batch), block(512);
    if (Ch)       gemm3<false, true ><<<grid, block, GEMM_SMEM>>>(Ah, Al, Bh, Bl, bias, C, Ch, Cl, M, N, K, alpha, sA, sB, sC);
    else if (bias) gemm3<true, false><<<grid, block, GEMM_SMEM>>>(Ah, Al, Bh, Bl, bias, C, Ch, Cl, M, N, K, alpha, sA, sB, sC);
    else          gemm3<false, false><<<grid, block, GEMM_SMEM>>>(Ah, Al, Bh, Bl, bias, C, Ch, Cl, M, N, K, alpha, sA, sB, sC);
}

static void tconv(const float* in, __nv_bfloat16* oh, __nv_bfloat16* ol, int R, int C) {
    dim3 grid(C / 32, R / 32), block(32, 8);
    tconvsplit<<<grid, block>>>(in, oh, ol, R, C);
}

// attention: out = LN( softmax((q@Wq)(ctx@Wk)^T/8) @ (ctx@Wv) + resid )
static void run_attn(const Ptrs& P,
                     const __nv_bfloat16* qh_in, const __nv_bfloat16* ql_in,
                     const __nv_bfloat16* ch_in, const __nv_bfloat16* cl_in,
                     const float* wq, const float* wk, const float* wv,
                     const float* resid, float* outp,
                     __nv_bfloat16* out_h, __nv_bfloat16* out_l)
{
    tconv(wq, P.wh, P.wl, Dm, Dm);
    G(qh_in, ql_in, P.wh, P.wl, nullptr, nullptr, P.qh, P.ql, ROWS, Dm, Dm, 1.f, 1, 0, 0, 0);
    tconv(wk, P.wh, P.wl, Dm, Dm);
    G(ch_in, cl_in, P.wh, P.wl, nullptr, nullptr, P.kh, P.kl, ROWS, Dm, Dm, 1.f, 1, 0, 0, 0);
    tconv(wv, P.wh, P.wl, Dm, Dm);
    G(ch_in, cl_in, P.wh, P.wl, nullptr, nullptr, P.vh, P.vl, ROWS, Dm, Dm, 1.f, 1, 0, 0, 0);

    // scores[b] = Q[b] @ K[b]^T / 8
    G(P.qh, P.ql, P.kh, P.kl, nullptr, P.gs, nullptr, nullptr, Sq, Sq, Dm, INV_SCALE, Bsz,
      (long)Sq * Dm, (long)Sq * Dm, (long)Sq * Sq);
    softmax_split_kernel<<<ROWS, 256>>>(P.gs, P.ph, P.pl, Sq);
    // V^T per batch
    {
        dim3 grid(Dm / 32, Sq / 32, Bsz), block(32, 8);
        tbf16<<<grid, block>>>(P.vh, P.vl, P.vth, P.vtl, Sq, Dm, (long)Sq * Dm);
    }
    // attn[b] = P[b] @ V[b]
    G(P.ph, P.pl, P.vth, P.vtl, nullptr, P.ga, nullptr, nullptr, Sq, Dm, Sq, 1.f, Bsz,
      (long)Sq * Sq, (long)Sq * Dm, (long)Sq * Dm);
    addln_kernel<false, false><<<ROWS, 128>>>(P.ga, resid, nullptr, nullptr, outp, out_h, out_l);
}

extern "C" void kernel_launch(void* const* d_in, const int* in_sizes, int n_in,
                              void* d_out, int out_size)
{
    const float* x       = (const float*)d_in[0];
    const float* y       = (const float*)d_in[1];
    const float* enc_wq  = (const float*)d_in[2];
    const float* enc_wk  = (const float*)d_in[3];
    const float* enc_wv  = (const float*)d_in[4];
    const float* enc_fw  = (const float*)d_in[5];
    const float* enc_fb  = (const float*)d_in[6];
    const float* enc_g   = (const float*)d_in[7];
    const float* enc_b   = (const float*)d_in[8];
    const float* dec_swq = (const float*)d_in[9];
    const float* dec_swk = (const float*)d_in[10];
    const float* dec_swv = (const float*)d_in[11];
    const float* dec_cwq = (const float*)d_in[12];
    const float* dec_cwk = (const float*)d_in[13];
    const float* dec_cwv = (const float*)d_in[14];
    const float* dec_fw  = (const float*)d_in[15];
    const float* dec_fb  = (const float*)d_in[16];
    const float* dec_g   = (const float*)d_in[17];
    const float* dec_b   = (const float*)d_in[18];
    const float* fc_w    = (const float*)d_in[19];

    cudaFuncSetAttribute(gemm3<false, false>, cudaFuncAttributeMaxDynamicSharedMemorySize, GEMM_SMEM);
    cudaFuncSetAttribute(gemm3<false, true >, cudaFuncAttributeMaxDynamicSharedMemorySize, GEMM_SMEM);
    cudaFuncSetAttribute(gemm3<true , false>, cudaFuncAttributeMaxDynamicSharedMemorySize, GEMM_SMEM);

    Ptrs P;
    cudaGetSymbolAddress((void**)&P.gx,   g_x);
    cudaGetSymbolAddress((void**)&P.gout, g_out);
    cudaGetSymbolAddress((void**)&P.gh,   g_h);
    cudaGetSymbolAddress((void**)&P.gh2,  g_h2);
    cudaGetSymbolAddress((void**)&P.gt,   g_t);
    cudaGetSymbolAddress((void**)&P.ga,   g_a);
    cudaGetSymbolAddress((void**)&P.gs,   g_s);
    cudaGetSymbolAddress((void**)&P.xh,  sx_h);   cudaGetSymbolAddress((void**)&P.xl,  sx_l);
    cudaGetSymbolAddress((void**)&P.oh,  so_h);   cudaGetSymbolAddress((void**)&P.ol,  so_l);
    cudaGetSymbolAddress((void**)&P.hh,  sh_h);   cudaGetSymbolAddress((void**)&P.hl,  sh_l);
    cudaGetSymbolAddress((void**)&P.h2h, sh2_h);  cudaGetSymbolAddress((void**)&P.h2l, sh2_l);
    cudaGetSymbolAddress((void**)&P.qh,  sq_h);   cudaGetSymbolAddress((void**)&P.ql,  sq_l);
    cudaGetSymbolAddress((void**)&P.kh,  sk_h);   cudaGetSymbolAddress((void**)&P.kl,  sk_l);
    cudaGetSymbolAddress((void**)&P.vh,  sv_h);   cudaGetSymbolAddress((void**)&P.vl,  sv_l);
    cudaGetSymbolAddress((void**)&P.vth, svt_h);  cudaGetSymbolAddress((void**)&P.vtl, svt_l);
    cudaGetSymbolAddress((void**)&P.ph,  sp_h);   cudaGetSymbolAddress((void**)&P.pl,  sp_l);
    cudaGetSymbolAddress((void**)&P.wh,  sw_h);   cudaGetSymbolAddress((void**)&P.wl,  sw_l);

    cudaMemcpyAsync(P.gx,   x, (size_t)BD * sizeof(float), cudaMemcpyDeviceToDevice);
    cudaMemcpyAsync(P.gout, y, (size_t)BD * sizeof(float), cudaMemcpyDeviceToDevice);
    convsplit<<<(BD / 4 + 255) / 256, 256>>>(x, P.xh, P.xl, BD);
    convsplit<<<(BD / 4 + 255) / 256, 256>>>(y, P.oh, P.ol, BD);

    const long DD = (long)Dm * Dm;

    // -------- encoder stacks --------
    for (int i = 0; i < Ll; i++) {
        run_attn(P, P.xh, P.xl, P.xh, P.xl,
                 enc_wq + i * DD, enc_wk + i * DD, enc_wv + i * DD,
                 P.gx, P.gh, P.hh, P.hl);
        tconv(enc_fw + i * DD, P.wh, P.wl, Dm, Dm);
        G(P.hh, P.hl, P.wh, P.wl, enc_fb + i * Dm, P.gt, nullptr, nullptr, ROWS, Dm, Dm, 1.f, 1, 0, 0, 0);
        addln_kernel<true, true><<<ROWS, 128>>>(P.gt, P.gh, enc_g + i * Dm, enc_b + i * Dm, P.gx, P.xh, P.xl);
    }

    // -------- decoder stacks --------
    for (int i = 0; i < Ll; i++) {
        run_attn(P, P.xh, P.xl, P.xh, P.xl,
                 dec_swq + i * DD, dec_swk + i * DD, dec_swv + i * DD,
                 P.gx, P.gh, P.hh, P.hl);
        run_attn(P, P.hh, P.hl, P.oh, P.ol,
                 dec_cwq + i * DD, dec_cwk + i * DD, dec_cwv + i * DD,
                 P.gh, P.gh2, P.h2h, P.h2l);
        tconv(dec_fw + i * DD, P.wh, P.wl, Dm, Dm);
        G(P.h2h, P.h2l, P.wh, P.wl, dec_fb + i * Dm, P.gt, nullptr, nullptr, ROWS, Dm, Dm, 1.f, 1, 0, 0, 0);
        addln_kernel<true, true><<<ROWS, 128>>>(P.gt, P.gh2, dec_g + i * Dm, dec_b + i * Dm, P.gout, P.oh, P.ol);
    }

    // -------- vocab head + softmax --------
    tconv(fc_w, P.wh, P.wl, Dm, Vv);
    float* logits = (float*)d_out;
    G(P.oh, P.ol, P.wh, P.wl, nullptr, logits, nullptr, nullptr, ROWS, Vv, Dm, 1.f, 1, 0, 0, 0);
    softmax_kernel<<<ROWS, 512>>>(logits, Vv);
}

// round 5
// speedup vs baseline: 3.2621x; 1.0919x over previous
#include <cuda_runtime.h>
#include <cuda_bf16.h>
#include <math.h>
#include <stdint.h>

// Problem constants
#define Bsz 2
#define Sq  2048
#define Dm  512
#define Vv  32000
#define Ll  3
#define ROWS (Bsz*Sq)      // 4096
#define BD   (ROWS*Dm)     // 2097152
#define SSZ  (Bsz*Sq*Sq)   // 8388608
#define INV_SCALE 0.125f

// ---------------- fp32 scratch ----------------
__device__ float g_x[BD];
__device__ float g_out[BD];
__device__ float g_h[BD];
__device__ float g_h2[BD];
__device__ float g_t[BD];
__device__ float g_a[BD];
__device__ float g_s[SSZ];

// ---------------- bf16 split scratch ----------------
__device__ __nv_bfloat16 sx_h[BD],  sx_l[BD];
__device__ __nv_bfloat16 so_h[BD],  so_l[BD];
__device__ __nv_bfloat16 sh_h[BD],  sh_l[BD];
__device__ __nv_bfloat16 sh2_h[BD], sh2_l[BD];
__device__ __nv_bfloat16 sq_h[BD],  sq_l[BD];
__device__ __nv_bfloat16 sk_h[BD],  sk_l[BD];
__device__ __nv_bfloat16 sv_h[BD],  sv_l[BD];
__device__ __nv_bfloat16 svt_h[BD], svt_l[BD];
__device__ __nv_bfloat16 sp_h[SSZ], sp_l[SSZ];
__device__ __nv_bfloat16 sw_h[(long)Vv*Dm], sw_l[(long)Vv*Dm];

// ================= helpers =================
__device__ __forceinline__ uint32_t smem_u32(const void* p) {
    uint32_t a;
    asm("{ .reg .u64 t; cvta.to.shared.u64 t, %1; cvt.u32.u64 %0, t; }" : "=r"(a) : "l"(p));
    return a;
}
#define CP_ASYNC(dst, src) asm volatile("cp.async.cg.shared.global [%0], [%1], 16;" :: "r"(dst), "l"(src) : "memory")
#define CP_COMMIT()        asm volatile("cp.async.commit_group;" ::: "memory")
#define CP_WAIT(n)         asm volatile("cp.async.wait_group %0;" :: "n"(n) : "memory")

__device__ __forceinline__ void ldmx4(uint32_t& r0, uint32_t& r1, uint32_t& r2, uint32_t& r3, uint32_t a) {
    asm volatile("ldmatrix.sync.aligned.m8n8.x4.shared.b16 {%0,%1,%2,%3}, [%4];"
                 : "=r"(r0), "=r"(r1), "=r"(r2), "=r"(r3) : "r"(a));
}
__device__ __forceinline__ void mma_bf16(float* d, const uint32_t* a, const uint32_t* b) {
    asm volatile(
        "mma.sync.aligned.m16n8k16.row.col.f32.bf16.bf16.f32 "
        "{%0,%1,%2,%3}, {%4,%5,%6,%7}, {%8,%9}, {%0,%1,%2,%3};"
        : "+f"(d[0]), "+f"(d[1]), "+f"(d[2]), "+f"(d[3])
        : "r"(a[0]), "r"(a[1]), "r"(a[2]), "r"(a[3]), "r"(b[0]), "r"(b[1]));
}
__device__ __forceinline__ void split1(float x, __nv_bfloat16& h, __nv_bfloat16& l) {
    h = __float2bfloat16(x);
    l = __float2bfloat16(x - __bfloat162float(h));
}
// SW128 swizzle for a 128-row x 64-bf16 (128B/row) tile. c = 16B chunk 0..7.
__device__ __forceinline__ uint32_t swz(int r, int c) {
    return (uint32_t)(r * 128 + ((c ^ (r & 7)) * 16));
}

// ================= GEMM: C = alpha * A @ B^T (+bias | split out) ============
// A: [M,K] bf16 hi/lo; B: [N,K] bf16 hi/lo. bf16x3: Ah*Bh + Ah*Bl + Al*Bh.
// BM=BN=128, BK=64, 256 threads (8 warps: 4 M x 2 N, warp tile 32x64),
// 3-stage cp.async pipeline, 192KB dynamic smem.
#define TILEB 16384
#define STAGEB (4*TILEB)
#define GEMM_SMEM (3*STAGEB)

template<bool HAS_BIAS, bool SPLIT>
__global__ void __launch_bounds__(256, 1) gemm3(
    const __nv_bfloat16* __restrict__ Ah, const __nv_bfloat16* __restrict__ Al,
    const __nv_bfloat16* __restrict__ Bh, const __nv_bfloat16* __restrict__ Bl,
    const float* __restrict__ bias,
    float* __restrict__ C, __nv_bfloat16* __restrict__ Ch, __nv_bfloat16* __restrict__ Cl,
    int M, int N, int K, float alpha, long sA, long sB, long sC)
{
    extern __shared__ char smem[];
    const uint32_t sb = smem_u32(smem);
    const int tid = threadIdx.x, lane = tid & 31, wid = tid >> 5;
    const int wm = wid >> 1, wn = wid & 1;          // 4 M-warps x 2 N-warps
    const int bz = blockIdx.z;
    Ah += (long)bz * sA;  Al += (long)bz * sA;
    Bh += (long)bz * sB;  Bl += (long)bz * sB;

    const long rA0 = (long)blockIdx.y * 128;
    const long rB0 = (long)blockIdx.x * 128;

    // loader: 1024 16B-chunks per 16KB subtile; 256 threads x 4 chunks each
    uint32_t soff[4];
    long goff[4];
    #pragma unroll
    for (int i = 0; i < 4; i++) {
        const int q = tid + i * 256;
        const int r = q >> 3, c = q & 7;
        soff[i] = swz(r, c);
        goff[i] = (long)r * K + c * 8;
    }
    const __nv_bfloat16* gAh = Ah + rA0 * K;
    const __nv_bfloat16* gAl = Al + rA0 * K;
    const __nv_bfloat16* gBh = Bh + rB0 * K;
    const __nv_bfloat16* gBl = Bl + rB0 * K;

    float acc[2][8][4];
    #pragma unroll
    for (int i = 0; i < 2; i++)
        #pragma unroll
        for (int j = 0; j < 8; j++)
            #pragma unroll
            for (int q = 0; q < 4; q++) acc[i][j][q] = 0.f;

    const int nk = K >> 6;

    auto load_tile = [&](int st, int k0) {
        const uint32_t s = sb + st * STAGEB;
        #pragma unroll
        for (int i = 0; i < 4; i++) {
            CP_ASYNC(s + 0*TILEB + soff[i], gAh + goff[i] + k0);
            CP_ASYNC(s + 1*TILEB + soff[i], gAl + goff[i] + k0);
            CP_ASYNC(s + 2*TILEB + soff[i], gBh + goff[i] + k0);
            CP_ASYNC(s + 3*TILEB + soff[i], gBl + goff[i] + k0);
        }
    };

    load_tile(0, 0);  CP_COMMIT();
    load_tile(1, 64); CP_COMMIT();

    int st = 0;
    for (int kt = 0; kt < nk; kt++) {
        if (kt + 1 < nk) { CP_WAIT(1); } else { CP_WAIT(0); }
        __syncthreads();
        if (kt + 2 < nk) {
            int st2 = st + 2; if (st2 >= 3) st2 -= 3;
            load_tile(st2, (kt + 2) << 6);
            CP_COMMIT();
        }

        const uint32_t s0  = sb + st * STAGEB;
        const uint32_t sAH = s0, sAL = s0 + TILEB, sBH = s0 + 2*TILEB, sBL = s0 + 3*TILEB;
        const int arow = wm * 32 + (lane & 15);
        const int brow = wn * 64 + ((lane >> 4) << 3) + (lane & 7);

        #pragma unroll
        for (int ks = 0; ks < 4; ks++) {
            const int achk = ks * 2 + (lane >> 4);
            const int bchk = ks * 2 + ((lane >> 3) & 1);
            uint32_t ah[2][4], al[2][4];
            #pragma unroll
            for (int mi = 0; mi < 2; mi++) {
                const uint32_t off = swz(arow + mi * 16, achk);
                ldmx4(ah[mi][0], ah[mi][1], ah[mi][2], ah[mi][3], sAH + off);
                ldmx4(al[mi][0], al[mi][1], al[mi][2], al[mi][3], sAL + off);
            }
            uint32_t bh[8][2], bl[8][2];
            #pragma unroll
            for (int nj = 0; nj < 4; nj++) {
                const uint32_t off = swz(brow + nj * 16, bchk);
                uint32_t t0, t1, t2, t3;
                ldmx4(t0, t1, t2, t3, sBH + off);
                bh[2*nj][0] = t0; bh[2*nj][1] = t1; bh[2*nj+1][0] = t2; bh[2*nj+1][1] = t3;
                ldmx4(t0, t1, t2, t3, sBL + off);
                bl[2*nj][0] = t0; bl[2*nj][1] = t1; bl[2*nj+1][0] = t2; bl[2*nj+1][1] = t3;
            }
            #pragma unroll
            for (int mi = 0; mi < 2; mi++)
                #pragma unroll
                for (int ni = 0; ni < 8; ni++) {
                    mma_bf16(acc[mi][ni], ah[mi], bh[ni]);
                    mma_bf16(acc[mi][ni], ah[mi], bl[ni]);
                    mma_bf16(acc[mi][ni], al[mi], bh[ni]);
                }
        }
        st++; if (st >= 3) st = 0;
    }

    // epilogue
    const long rbase = rA0 + wm * 32 + (lane >> 2);
    const int  cbase = blockIdx.x * 128 + wn * 64 + (lane & 3) * 2;
    #pragma unroll
    for (int mi = 0; mi < 2; mi++) {
        #pragma unroll
        for (int ni = 0; ni < 8; ni++) {
            const int cc = cbase + ni * 8;
            float v00 = alpha * acc[mi][ni][0], v01 = alpha * acc[mi][ni][1];
            float v10 = alpha * acc[mi][ni][2], v11 = alpha * acc[mi][ni][3];
            if (HAS_BIAS) {
                v00 += bias[cc]; v01 += bias[cc + 1];
                v10 += bias[cc]; v11 += bias[cc + 1];
            }
            const long r0 = (long)bz * sC + (rbase + mi * 16) * N;
            const long r1 = r0 + 8 * N;
            if (SPLIT) {
                __nv_bfloat16 h0, l0, h1, l1;
                split1(v00, h0, l0); split1(v01, h1, l1);
                *(__nv_bfloat162*)(Ch + r0 + cc) = {h0, h1};
                *(__nv_bfloat162*)(Cl + r0 + cc) = {l0, l1};
                split1(v10, h0, l0); split1(v11, h1, l1);
                *(__nv_bfloat162*)(Ch + r1 + cc) = {h0, h1};
                *(__nv_bfloat162*)(Cl + r1 + cc) = {l0, l1};
            } else {
                *(float2*)(C + r0 + cc) = {v00, v01};
                *(float2*)(C + r1 + cc) = {v10, v11};
            }
        }
    }
}

// ================= conversion kernels =================
__global__ void convsplit(const float* __restrict__ in,
                          __nv_bfloat16* __restrict__ oh, __nv_bfloat16* __restrict__ ol, long n)
{
    long i = ((long)blockIdx.x * blockDim.x + threadIdx.x) * 4;
    if (i >= n) return;
    float4 v = *(const float4*)(in + i);
    __nv_bfloat16 h0, h1, h2, h3, l0, l1, l2, l3;
    split1(v.x, h0, l0); split1(v.y, h1, l1); split1(v.z, h2, l2); split1(v.w, h3, l3);
    __nv_bfloat162 hh0 = {h0, h1}, hh1 = {h2, h3}, ll0 = {l0, l1}, ll1 = {l2, l3};
    *(uint2*)(oh + i) = make_uint2(*(uint32_t*)&hh0, *(uint32_t*)&hh1);
    *(uint2*)(ol + i) = make_uint2(*(uint32_t*)&ll0, *(uint32_t*)&ll1);
}

// transpose + split: fp32 [R,C] -> bf16 hi/lo [C,R]
__global__ void __launch_bounds__(256) tconvsplit(
    const float* __restrict__ in, __nv_bfloat16* __restrict__ oh, __nv_bfloat16* __restrict__ ol,
    int R, int C)
{
    __shared__ float t[32][33];
    const int c0 = blockIdx.x * 32, r0 = blockIdx.y * 32;
    const int tx = threadIdx.x, ty = threadIdx.y;
    #pragma unroll
    for (int j = 0; j < 32; j += 8)
        t[ty + j][tx] = in[(long)(r0 + ty + j) * C + c0 + tx];
    __syncthreads();
    #pragma unroll
    for (int j = 0; j < 32; j += 8) {
        float v = t[tx][ty + j];
        __nv_bfloat16 h, l;
        split1(v, h, l);
        long o = (long)(c0 + ty + j) * R + r0 + tx;
        oh[o] = h; ol[o] = l;
    }
}

// bf16 pair transpose: [R,C] -> [C,R], batched
__global__ void __launch_bounds__(256) tbf16(
    const __nv_bfloat16* __restrict__ ih, const __nv_bfloat16* __restrict__ il,
    __nv_bfloat16* __restrict__ oh, __nv_bfloat16* __restrict__ ol,
    int R, int C, long sIO)
{
    __shared__ __nv_bfloat16 th[32][33], tl[32][33];
    ih += (long)blockIdx.z * sIO;  il += (long)blockIdx.z * sIO;
    oh += (long)blockIdx.z * sIO;  ol += (long)blockIdx.z * sIO;
    const int c0 = blockIdx.x * 32, r0 = blockIdx.y * 32;
    const int tx = threadIdx.x, ty = threadIdx.y;
    #pragma unroll
    for (int j = 0; j < 32; j += 8) {
        long idx = (long)(r0 + ty + j) * C + c0 + tx;
        th[ty + j][tx] = ih[idx];
        tl[ty + j][tx] = il[idx];
    }
    __syncthreads();
    #pragma unroll
    for (int j = 0; j < 32; j += 8) {
        long o = (long)(c0 + ty + j) * R + r0 + tx;
        oh[o] = th[tx][ty + j];
        ol[o] = tl[tx][ty + j];
    }
}

// ================= online softmax =================
__device__ __forceinline__ void sm_merge(float& m, float& s, float m2, float s2) {
    float M = fmaxf(m, m2);
    s = s * __expf(m - M) + s2 * __expf(m2 - M);
    m = M;
}
__device__ __forceinline__ void block_softmax_stats(float& m, float& s) {
    __shared__ float shm[32], shs[32];
    const int lane = threadIdx.x & 31, w = threadIdx.x >> 5;
    #pragma unroll
    for (int o = 16; o; o >>= 1)
        sm_merge(m, s, __shfl_xor_sync(0xffffffffu, m, o), __shfl_xor_sync(0xffffffffu, s, o));
    if (lane == 0) { shm[w] = m; shs[w] = s; }
    __syncthreads();
    const int nw = blockDim.x >> 5;
    if (w == 0) {
        float mm = (lane < nw) ? shm[lane] : -1e30f;
        float ss = (lane < nw) ? shs[lane] : 0.f;
        #pragma unroll
        for (int o = 16; o; o >>= 1)
            sm_merge(mm, ss, __shfl_xor_sync(0xffffffffu, mm, o), __shfl_xor_sync(0xffffffffu, ss, o));
        if (lane == 0) { shm[0] = mm; shs[0] = ss; }
    }
    __syncthreads();
    m = shm[0]; s = shs[0];
    __syncthreads();
}

__global__ void softmax_kernel(float* __restrict__ data, int N) {
    float* row = data + (size_t)blockIdx.x * N;
    float m = -1e30f, s = 0.f;
    for (int i = threadIdx.x; i < N; i += blockDim.x) {
        float v = row[i];
        float mo = m;
        m = fmaxf(m, v);
        s = s * __expf(mo - m) + __expf(v - m);
    }
    block_softmax_stats(m, s);
    const float inv = 1.f / s;
    for (int i = threadIdx.x; i < N; i += blockDim.x)
        row[i] = __expf(row[i] - m) * inv;
}

__global__ void softmax_split_kernel(const float* __restrict__ in,
                                     __nv_bfloat16* __restrict__ oh, __nv_bfloat16* __restrict__ ol, int N)
{
    const float* row = in + (size_t)blockIdx.x * N;
    float m = -1e30f, s = 0.f;
    for (int i = threadIdx.x; i < N; i += blockDim.x) {
        float v = row[i];
        float mo = m;
        m = fmaxf(m, v);
        s = s * __expf(mo - m) + __expf(v - m);
    }
    block_softmax_stats(m, s);
    const float inv = 1.f / s;
    const size_t base = (size_t)blockIdx.x * N;
    for (int i = threadIdx.x; i < N; i += blockDim.x) {
        float p = __expf(row[i] - m) * inv;
        __nv_bfloat16 h, l;
        split1(p, h, l);
        oh[base + i] = h; ol[base + i] = l;
    }
}

// ========== fused (silu?)+residual+LayerNorm, fp32 out + split out ==========
template<bool SILU, bool AFFINE>
__global__ void __launch_bounds__(128) addln_kernel(
    const float* __restrict__ a, const float* __restrict__ res,
    const float* __restrict__ g, const float* __restrict__ bta,
    float* __restrict__ out, __nv_bfloat16* __restrict__ oh, __nv_bfloat16* __restrict__ ol)
{
    const int row = blockIdx.x;
    const int tid = threadIdx.x;
    float4 av = ((const float4*)(a   + (size_t)row * Dm))[tid];
    float4 rv = ((const float4*)(res + (size_t)row * Dm))[tid];
    float v[4] = {av.x, av.y, av.z, av.w};
    float r[4] = {rv.x, rv.y, rv.z, rv.w};

    float s = 0.f, s2 = 0.f;
    #pragma unroll
    for (int i = 0; i < 4; i++) {
        float t = SILU ? (v[i] / (1.f + __expf(-v[i]))) : v[i];
        t += r[i];
        v[i] = t;
        s += t; s2 += t * t;
    }
    __shared__ float ss[4], ss2[4];
    #pragma unroll
    for (int o = 16; o; o >>= 1) {
        s  += __shfl_xor_sync(0xffffffffu, s,  o);
        s2 += __shfl_xor_sync(0xffffffffu, s2, o);
    }
    const int w = tid >> 5, lane = tid & 31;
    if (lane == 0) { ss[w] = s; ss2[w] = s2; }
    __syncthreads();
    s  = ss[0]  + ss[1]  + ss[2]  + ss[3];
    s2 = ss2[0] + ss2[1] + ss2[2] + ss2[3];

    const float mean = s * (1.f / Dm);
    const float var  = s2 * (1.f / Dm) - mean * mean;
    const float inv  = rsqrtf(var + 1e-5f);

    float ov[4];
    __nv_bfloat16 hh[4], ll[4];
    #pragma unroll
    for (int i = 0; i < 4; i++) {
        float yv = (v[i] - mean) * inv;
        if (AFFINE) {
            const int c = tid * 4 + i;
            yv = yv * g[c] + bta[c];
        }
        ov[i] = yv;
        split1(yv, hh[i], ll[i]);
    }
    float4 o4 = {ov[0], ov[1], ov[2], ov[3]};
    ((float4*)(out + (size_t)row * Dm))[tid] = o4;
    __nv_bfloat162 h0 = {hh[0], hh[1]}, h1 = {hh[2], hh[3]};
    __nv_bfloat162 l0 = {ll[0], ll[1]}, l1 = {ll[2], ll[3]};
    ((uint2*)(oh + (size_t)row * Dm))[tid] = make_uint2(*(uint32_t*)&h0, *(uint32_t*)&h1);
    ((uint2*)(ol + (size_t)row * Dm))[tid] = make_uint2(*(uint32_t*)&l0, *(uint32_t*)&l1);
}

// ================= host-side orchestration =================
struct Ptrs {
    float *gx, *gout, *gh, *gh2, *gt, *ga, *gs;
    __nv_bfloat16 *xh, *xl, *oh, *ol, *hh, *hl, *h2h, *h2l;
    __nv_bfloat16 *qh, *ql, *kh, *kl, *vh, *vl, *vth, *vtl, *ph, *pl, *wh, *wl;
};

static void G(const __nv_bfloat16* Ah, const __nv_bfloat16* Al,
              const __nv_bfloat16* Bh, const __nv_bfloat16* Bl,
              const float* bias, float* C, __nv_bfloat16* Ch, __nv_bfloat16* Cl,
              int M, int N, int K, float alpha, int batch,
              long sA, long sB, long sC)
{
    dim3 grid(N / 128, M / 128, batch), block(256);
    if (Ch)        gemm3<false, true ><<<grid, block, GEMM_SMEM>>>(Ah, Al, Bh, Bl, bias, C, Ch, Cl, M, N, K, alpha, sA, sB, sC);
    else if (bias) gemm3<true , false><<<grid, block, GEMM_SMEM>>>(Ah, Al, Bh, Bl, bias, C, Ch, Cl, M, N, K, alpha, sA, sB, sC);
    else           gemm3<false, false><<<grid, block, GEMM_SMEM>>>(Ah, Al, Bh, Bl, bias, C, Ch, Cl, M, N, K, alpha, sA, sB, sC);
}

static void tconv(const float* in, __nv_bfloat16* oh, __nv_bfloat16* ol, int R, int C) {
    dim3 grid(C / 32, R / 32), block(32, 8);
    tconvsplit<<<grid, block>>>(in, oh, ol, R, C);
}

static void run_attn(const Ptrs& P,
                     const __nv_bfloat16* qh_in, const __nv_bfloat16* ql_in,
                     const __nv_bfloat16* ch_in, const __nv_bfloat16* cl_in,
                     const float* wq, const float* wk, const float* wv,
                     const float* resid, float* outp,
                     __nv_bfloat16* out_h, __nv_bfloat16* out_l)
{
    tconv(wq, P.wh, P.wl, Dm, Dm);
    G(qh_in, ql_in, P.wh, P.wl, nullptr, nullptr, P.qh, P.ql, ROWS, Dm, Dm, 1.f, 1, 0, 0, 0);
    tconv(wk, P.wh, P.wl, Dm, Dm);
    G(ch_in, cl_in, P.wh, P.wl, nullptr, nullptr, P.kh, P.kl, ROWS, Dm, Dm, 1.f, 1, 0, 0, 0);
    tconv(wv, P.wh, P.wl, Dm, Dm);
    G(ch_in, cl_in, P.wh, P.wl, nullptr, nullptr, P.vh, P.vl, ROWS, Dm, Dm, 1.f, 1, 0, 0, 0);

    G(P.qh, P.ql, P.kh, P.kl, nullptr, P.gs, nullptr, nullptr, Sq, Sq, Dm, INV_SCALE, Bsz,
      (long)Sq * Dm, (long)Sq * Dm, (long)Sq * Sq);
    softmax_split_kernel<<<ROWS, 256>>>(P.gs, P.ph, P.pl, Sq);
    {
        dim3 grid(Dm / 32, Sq / 32, Bsz), block(32, 8);
        tbf16<<<grid, block>>>(P.vh, P.vl, P.vth, P.vtl, Sq, Dm, (long)Sq * Dm);
    }
    G(P.ph, P.pl, P.vth, P.vtl, nullptr, P.ga, nullptr, nullptr, Sq, Dm, Sq, 1.f, Bsz,
      (long)Sq * Sq, (long)Sq * Dm, (long)Sq * Dm);
    addln_kernel<false, false><<<ROWS, 128>>>(P.ga, resid, nullptr, nullptr, outp, out_h, out_l);
}

extern "C" void kernel_launch(void* const* d_in, const int* in_sizes, int n_in,
                              void* d_out, int out_size)
{
    const float* x       = (const float*)d_in[0];
    const float* y       = (const float*)d_in[1];
    const float* enc_wq  = (const float*)d_in[2];
    const float* enc_wk  = (const float*)d_in[3];
    const float* enc_wv  = (const float*)d_in[4];
    const float* enc_fw  = (const float*)d_in[5];
    const float* enc_fb  = (const float*)d_in[6];
    const float* enc_g   = (const float*)d_in[7];
    const float* enc_b   = (const float*)d_in[8];
    const float* dec_swq = (const float*)d_in[9];
    const float* dec_swk = (const float*)d_in[10];
    const float* dec_swv = (const float*)d_in[11];
    const float* dec_cwq = (const float*)d_in[12];
    const float* dec_cwk = (const float*)d_in[13];
    const float* dec_cwv = (const float*)d_in[14];
    const float* dec_fw  = (const float*)d_in[15];
    const float* dec_fb  = (const float*)d_in[16];
    const float* dec_g   = (const float*)d_in[17];
    const float* dec_b   = (const float*)d_in[18];
    const float* fc_w    = (const float*)d_in[19];

    cudaFuncSetAttribute(gemm3<false, false>, cudaFuncAttributeMaxDynamicSharedMemorySize, GEMM_SMEM);
    cudaFuncSetAttribute(gemm3<false, true >, cudaFuncAttributeMaxDynamicSharedMemorySize, GEMM_SMEM);
    cudaFuncSetAttribute(gemm3<true , false>, cudaFuncAttributeMaxDynamicSharedMemorySize, GEMM_SMEM);

    Ptrs P;
    cudaGetSymbolAddress((void**)&P.gx,   g_x);
    cudaGetSymbolAddress((void**)&P.gout, g_out);
    cudaGetSymbolAddress((void**)&P.gh,   g_h);
    cudaGetSymbolAddress((void**)&P.gh2,  g_h2);
    cudaGetSymbolAddress((void**)&P.gt,   g_t);
    cudaGetSymbolAddress((void**)&P.ga,   g_a);
    cudaGetSymbolAddress((void**)&P.gs,   g_s);
    cudaGetSymbolAddress((void**)&P.xh,  sx_h);   cudaGetSymbolAddress((void**)&P.xl,  sx_l);
    cudaGetSymbolAddress((void**)&P.oh,  so_h);   cudaGetSymbolAddress((void**)&P.ol,  so_l);
    cudaGetSymbolAddress((void**)&P.hh,  sh_h);   cudaGetSymbolAddress((void**)&P.hl,  sh_l);
    cudaGetSymbolAddress((void**)&P.h2h, sh2_h);  cudaGetSymbolAddress((void**)&P.h2l, sh2_l);
    cudaGetSymbolAddress((void**)&P.qh,  sq_h);   cudaGetSymbolAddress((void**)&P.ql,  sq_l);
    cudaGetSymbolAddress((void**)&P.kh,  sk_h);   cudaGetSymbolAddress((void**)&P.kl,  sk_l);
    cudaGetSymbolAddress((void**)&P.vh,  sv_h);   cudaGetSymbolAddress((void**)&P.vl,  sv_l);
    cudaGetSymbolAddress((void**)&P.vth, svt_h);  cudaGetSymbolAddress((void**)&P.vtl, svt_l);
    cudaGetSymbolAddress((void**)&P.ph,  sp_h);   cudaGetSymbolAddress((void**)&P.pl,  sp_l);
    cudaGetSymbolAddress((void**)&P.wh,  sw_h);   cudaGetSymbolAddress((void**)&P.wl,  sw_l);

    cudaMemcpyAsync(P.gx,   x, (size_t)BD * sizeof(float), cudaMemcpyDeviceToDevice);
    cudaMemcpyAsync(P.gout, y, (size_t)BD * sizeof(float), cudaMemcpyDeviceToDevice);
    convsplit<<<(BD / 4 + 255) / 256, 256>>>(x, P.xh, P.xl, BD);
    convsplit<<<(BD / 4 + 255) / 256, 256>>>(y, P.oh, P.ol, BD);

    const long DD = (long)Dm * Dm;

    // -------- encoder stacks --------
    for (int i = 0; i < Ll; i++) {
        run_attn(P, P.xh, P.xl, P.xh, P.xl,
                 enc_wq + i * DD, enc_wk + i * DD, enc_wv + i * DD,
                 P.gx, P.gh, P.hh, P.hl);
        tconv(enc_fw + i * DD, P.wh, P.wl, Dm, Dm);
        G(P.hh, P.hl, P.wh, P.wl, enc_fb + i * Dm, P.gt, nullptr, nullptr, ROWS, Dm, Dm, 1.f, 1, 0, 0, 0);
        addln_kernel<true, true><<<ROWS, 128>>>(P.gt, P.gh, enc_g + i * Dm, enc_b + i * Dm, P.gx, P.xh, P.xl);
    }

    // -------- decoder stacks --------
    for (int i = 0; i < Ll; i++) {
        run_attn(P, P.xh, P.xl, P.xh, P.xl,
                 dec_swq + i * DD, dec_swk + i * DD, dec_swv + i * DD,
                 P.gx, P.gh, P.hh, P.hl);
        run_attn(P, P.hh, P.hl, P.oh, P.ol,
                 dec_cwq + i * DD, dec_cwk + i * DD, dec_cwv + i * DD,
                 P.gh, P.gh2, P.h2h, P.h2l);
        tconv(dec_fw + i * DD, P.wh, P.wl, Dm, Dm);
        G(P.h2h, P.h2l, P.wh, P.wl, dec_fb + i * Dm, P.gt, nullptr, nullptr, ROWS, Dm, Dm, 1.f, 1, 0, 0, 0);
        addln_kernel<true, true><<<ROWS, 128>>>(P.gt, P.gh2, dec_g + i * Dm, dec_b + i * Dm, P.gout, P.oh, P.ol);
    }

    // -------- vocab head + softmax --------
    tconv(fc_w, P.wh, P.wl, Dm, Vv);
    float* logits = (float*)d_out;
    G(P.oh, P.ol, P.wh, P.wl, nullptr, logits, nullptr, nullptr, ROWS, Vv, Dm, 1.f, 1, 0, 0, 0);
    softmax_kernel<<<ROWS, 512>>>(logits, Vv);
}